// round 5
// baseline (speedup 1.0000x reference)
#include <cuda_runtime.h>
#include <cuda.h>
#include <cstdint>

// ---------------- constants ----------------
#define NUMF    41024
#define KCHUNK  64                  // floats per pipeline chunk
#define NCHUNK  (NUMF / KCHUNK)     // 641 exact
#define STAGES  3
#define STAGE_BYTES 65536           // A(2x16KB) + B(2x16KB)
#define SMEM1   (1024 + 1024 + STAGES * STAGE_BYTES)   // 198656
#define SWZ(b)  ((b) ^ (((b) >> 3) & 0x70))            // SW128 swizzle

__device__ float g_acc[8192 * 256]; // rows 0..4095 white acc(+b0), 4096..8191 black

// ---------------- device helpers ----------------
__device__ __forceinline__ uint32_t smem_u32(const void* p) {
    uint32_t a;
    asm("{ .reg .u64 t; cvta.to.shared.u64 t, %1; cvt.u32.u64 %0, t; }" : "=r"(a) : "l"(p));
    return a;
}
__device__ __forceinline__ void mbar_init(uint32_t a, uint32_t c) {
    asm volatile("mbarrier.init.shared.b64 [%0], %1;" :: "r"(a), "r"(c) : "memory");
}
__device__ __forceinline__ void mbar_expect_tx(uint32_t a, uint32_t b) {
    asm volatile("mbarrier.arrive.expect_tx.shared.b64 _, [%0], %1;" :: "r"(a), "r"(b) : "memory");
}
__device__ __forceinline__ void mbar_arrive(uint32_t a) {
    asm volatile("mbarrier.arrive.shared.b64 _, [%0];" :: "r"(a) : "memory");
}
__device__ __forceinline__ void mbar_wait(uint32_t mbar, uint32_t parity) {
    asm volatile(
        "{\n\t.reg .pred P;\n\t"
        "LW_%=:\n\t"
        "mbarrier.try_wait.parity.acquire.cta.shared::cta.b64 P, [%0], %1, 0x989680;\n\t"
        "@P bra.uni LD_%=;\n\t"
        "bra.uni LW_%=;\n\t"
        "LD_%=:\n\t}"
        :: "r"(mbar), "r"(parity) : "memory");
}
__device__ __forceinline__ void tma2d(uint32_t dst, const CUtensorMap* m, int x, int y, uint32_t mbar) {
    asm volatile(
        "cp.async.bulk.tensor.2d.shared::cta.global.tile.mbarrier::complete_tx::bytes "
        "[%0], [%1, {%2, %3}], [%4];"
        :: "r"(dst), "l"(m), "r"(x), "r"(y), "r"(mbar) : "memory");
}
__device__ __forceinline__ uint32_t f2tf32(float x) {
    uint32_t r;
    asm("cvt.rna.tf32.f32 %0, %1;" : "=r"(r) : "f"(x));
    return r;
}
__device__ __forceinline__ void mma_tf32(float* c, const uint32_t* a, const uint32_t* b) {
    asm volatile(
        "mma.sync.aligned.m16n8k8.row.col.f32.tf32.tf32.f32 "
        "{%0,%1,%2,%3}, {%4,%5,%6,%7}, {%8,%9}, {%0,%1,%2,%3};"
        : "+f"(c[0]), "+f"(c[1]), "+f"(c[2]), "+f"(c[3])
        : "r"(a[0]), "r"(a[1]), "r"(a[2]), "r"(a[3]), "r"(b[0]), "r"(b[1]));
}

// ---------------- kernel 1: layer-0 GEMM (tf32 mma.sync) ----------------
// 128 CTAs: bid = mt*2 + nt. mt 0..31 -> white rows, 32..63 -> black rows.
// CTA tile 128(M feature rows) x 128(N neurons), K = 41024 streamed via TMA.
// 160 threads: warps 0-3 consumers (64x64 warp tiles), warp 4 lane 0 producer.
__global__ void __launch_bounds__(160, 1) nn_gemm(
    const __grid_constant__ CUtensorMap tmW,
    const __grid_constant__ CUtensorMap tmB,
    const __grid_constant__ CUtensorMap tmW0,
    const float* __restrict__ b0)
{
    extern __shared__ char raw[];
    char* base = (char*)(((uintptr_t)raw + 1023u) & ~(uintptr_t)1023u);
    uint32_t base_u  = smem_u32(base);
    uint32_t mb_full = base_u;          // 3 x 8B
    uint32_t mb_empty = base_u + 64;    // 3 x 8B
    char* tiles      = base + 1024;
    uint32_t tiles_u = base_u + 1024;

    const int tid  = threadIdx.x;
    const int bid  = blockIdx.x;
    const int nt   = bid & 1, mt = bid >> 1;
    const int row0 = (mt & 31) * 128;   // feature row within side
    const int n0   = nt * 128;          // W0 row (output neuron)
    const CUtensorMap* tmaA = (mt < 32) ? &tmW : &tmB;

    if (tid == 0) {
        for (int s = 0; s < STAGES; s++) {
            mbar_init(mb_full  + s * 8, 1);
            mbar_init(mb_empty + s * 8, 128);   // 128 consumer threads arrive
        }
        asm volatile("fence.proxy.async.shared::cta;" ::: "memory");
    }
    __syncthreads();

    if (tid == 128) {
        // ---------------- producer ----------------
#define ISSUE(kc_, s_) do {                                          \
            uint32_t mb_ = mb_full + (s_) * 8;                       \
            mbar_expect_tx(mb_, STAGE_BYTES);                        \
            uint32_t t_ = tiles_u + (s_) * STAGE_BYTES;              \
            int x_ = (kc_) * KCHUNK;                                 \
            tma2d(t_,         tmaA,  x_,      row0, mb_);            \
            tma2d(t_ + 16384, tmaA,  x_ + 32, row0, mb_);            \
            tma2d(t_ + 32768, &tmW0, x_,      n0,   mb_);            \
            tma2d(t_ + 49152, &tmW0, x_ + 32, n0,   mb_);            \
        } while (0)
        ISSUE(0, 0); ISSUE(1, 1); ISSUE(2, 2);
        int ep[3] = {0, 0, 0};
        for (int k = STAGES; k < NCHUNK; k++) {
            int s = k % 3;
            mbar_wait(mb_empty + s * 8, ep[s]); ep[s] ^= 1;
            ISSUE(k, s);
        }
#undef ISSUE
    } else if (tid < 128) {
        // ---------------- consumers ----------------
        const int wid = tid >> 5;
        const int wm  = (wid >> 1) * 64;     // warp M offset
        const int wn  = (wid & 1) * 64;      // warp N offset
        const int qr  = (tid & 31) >> 2;     // lane / 4
        const int qc  = tid & 3;             // lane % 4

        float c[4][8][4];
        #pragma unroll
        for (int mi = 0; mi < 4; mi++)
            #pragma unroll
            for (int ni = 0; ni < 8; ni++)
                #pragma unroll
                for (int r = 0; r < 4; r++) c[mi][ni][r] = 0.f;

        int fp[3] = {0, 0, 0};
        for (int k = 0; k < NCHUNK; k++) {
            int s = k % 3;
            mbar_wait(mb_full + s * 8, fp[s]); fp[s] ^= 1;
            const char* stg = tiles + s * STAGE_BYTES;

            #pragma unroll
            for (int ks = 0; ks < 8; ks++) {
                const char* Ab = stg + (ks >> 2) * 16384;
                const char* Bb = stg + 32768 + (ks >> 2) * 16384;
                const int kb = ((ks & 3) * 8 + qc) * 4;   // byte offset of this lane's k col

                uint32_t a[4][4];
                #pragma unroll
                for (int mi = 0; mi < 4; mi++) {
                    int r = wm + mi * 16 + qr;
                    a[mi][0] = f2tf32(*(const float*)(Ab + SWZ( r      * 128 + kb)));
                    a[mi][1] = f2tf32(*(const float*)(Ab + SWZ((r + 8) * 128 + kb)));
                    a[mi][2] = f2tf32(*(const float*)(Ab + SWZ( r      * 128 + kb + 16)));
                    a[mi][3] = f2tf32(*(const float*)(Ab + SWZ((r + 8) * 128 + kb + 16)));
                }
                uint32_t b[8][2];
                #pragma unroll
                for (int ni = 0; ni < 8; ni++) {
                    int r = wn + ni * 8 + qr;
                    b[ni][0] = f2tf32(*(const float*)(Bb + SWZ(r * 128 + kb)));
                    b[ni][1] = f2tf32(*(const float*)(Bb + SWZ(r * 128 + kb + 16)));
                }
                #pragma unroll
                for (int mi = 0; mi < 4; mi++)
                    #pragma unroll
                    for (int ni = 0; ni < 8; ni++)
                        mma_tf32(c[mi][ni], a[mi], b[ni]);
            }
            mbar_arrive(mb_empty + s * 8);
        }

        // epilogue: add b0, write to g_acc
        #pragma unroll
        for (int ni = 0; ni < 8; ni++) {
            int col = n0 + wn + ni * 8 + qc * 2;
            float b0a = b0[col], b0b = b0[col + 1];
            #pragma unroll
            for (int mi = 0; mi < 4; mi++) {
                int row = mt * 128 + wm + mi * 16 + qr;
                float2 v0 = { c[mi][ni][0] + b0a, c[mi][ni][1] + b0b };
                float2 v1 = { c[mi][ni][2] + b0a, c[mi][ni][3] + b0b };
                *(float2*)(g_acc + (size_t)row * 256 + col)       = v0;
                *(float2*)(g_acc + (size_t)(row + 8) * 256 + col) = v1;
            }
        }
    }
}

// ---------------- kernel 2: blend + clip + small MLP head ----------------
#define SW1_PITCH 513
#define SW2_PITCH 33
#define SMEM2 ((32*SW1_PITCH + 32*SW2_PITCH + 8*512 + 8*32) * 4)

__global__ void __launch_bounds__(256) nn_head(
    const float* __restrict__ stm,
    const float* __restrict__ W1, const float* __restrict__ b1,
    const float* __restrict__ W2, const float* __restrict__ b2,
    const float* __restrict__ W3, const float* __restrict__ b3,
    float* __restrict__ out)
{
    extern __shared__ float sm[];
    float* sW1 = sm;                               // 32 x 513
    float* sW2 = sW1 + 32 * SW1_PITCH;             // 32 x 33
    float* sl1 = sW2 + 32 * SW2_PITCH;             // 8 warps x 512
    float* sl2 = sl1 + 8 * 512;                    // 8 warps x 32

    int tid = threadIdx.x;
    for (int i = tid; i < 32 * 512; i += 256) sW1[(i >> 9) * SW1_PITCH + (i & 511)] = W1[i];
    for (int i = tid; i < 32 * 32;  i += 256) sW2[(i >> 5) * SW2_PITCH + (i & 31)]  = W2[i];
    __syncthreads();

    int w = tid >> 5, j = tid & 31;
    float* l1 = sl1 + w * 512;
    float* l2 = sl2 + w * 32;
    float bj1 = b1[j], bj2 = b2[j], w3j = W3[j], b3v = b3[0];

    for (int q = 0; q < 4; q++) {
        int b = blockIdx.x * 32 + w * 4 + q;
        const float* aw = g_acc + (size_t)b * 256;
        const float* ab = g_acc + (size_t)(4096 + b) * 256;
        float s = stm[b];
        for (int t = j; t < 256; t += 32) {
            float wv = aw[t], bv = ab[t];
            float x0 = s * wv + (1.f - s) * bv;
            float x1 = s * bv + (1.f - s) * wv;
            l1[t]       = fminf(fmaxf(x0, 0.f), 1.f);
            l1[256 + t] = fminf(fmaxf(x1, 0.f), 1.f);
        }
        __syncwarp();
        float a2 = bj1;
        const float* wr = sW1 + j * SW1_PITCH;
        #pragma unroll 8
        for (int k = 0; k < 512; k++) a2 += wr[k] * l1[k];
        a2 = fminf(fmaxf(a2, 0.f), 1.f);
        l2[j] = a2;
        __syncwarp();
        float a3 = bj2;
        const float* wr2 = sW2 + j * SW2_PITCH;
        #pragma unroll
        for (int k = 0; k < 32; k++) a3 += wr2[k] * l2[k];
        a3 = fminf(fmaxf(a3, 0.f), 1.f);
        float v = w3j * a3;
        #pragma unroll
        for (int o = 16; o > 0; o >>= 1) v += __shfl_xor_sync(0xffffffffu, v, o);
        if (j == 0) out[b] = v + b3v;
        __syncwarp();
    }
}

// ---------------- host ----------------
typedef CUresult (*EncodeFn)(CUtensorMap*, CUtensorMapDataType, cuuint32_t, void*,
                             const cuuint64_t*, const cuuint64_t*, const cuuint32_t*, const cuuint32_t*,
                             CUtensorMapInterleave, CUtensorMapSwizzle,
                             CUtensorMapL2promotion, CUtensorMapFloatOOBfill);

static void encode_map(CUtensorMap* m, const void* ptr, unsigned long long rows) {
    void* p = nullptr;
    cudaDriverEntryPointQueryResult qr;
    cudaGetDriverEntryPointByVersion("cuTensorMapEncodeTiled", &p, 12000, cudaEnableDefault, &qr);
    EncodeFn fn = (EncodeFn)p;
    cuuint64_t dims[2]    = { (cuuint64_t)NUMF, (cuuint64_t)rows };
    cuuint64_t strides[1] = { (cuuint64_t)NUMF * 4ull };
    cuuint32_t box[2]     = { 32u, 128u };      // 128B x 128 rows, SW128
    cuuint32_t es[2]      = { 1u, 1u };
    fn(m, CU_TENSOR_MAP_DATA_TYPE_FLOAT32, 2, (void*)ptr, dims, strides, box, es,
       CU_TENSOR_MAP_INTERLEAVE_NONE, CU_TENSOR_MAP_SWIZZLE_128B,
       CU_TENSOR_MAP_L2_PROMOTION_L2_128B, CU_TENSOR_MAP_FLOAT_OOB_FILL_NONE);
}

extern "C" void kernel_launch(void* const* d_in, const int* in_sizes, int n_in,
                              void* d_out, int out_size) {
    const float* wf  = (const float*)d_in[0];
    const float* bf  = (const float*)d_in[1];
    const float* stm = (const float*)d_in[2];
    const float* b0  = (const float*)d_in[4];
    const float* W1  = (const float*)d_in[5];
    const float* b1  = (const float*)d_in[6];
    const float* W2  = (const float*)d_in[7];
    const float* b2  = (const float*)d_in[8];
    const float* W3  = (const float*)d_in[9];
    const float* b3  = (const float*)d_in[10];
    float* out = (float*)d_out;

    CUtensorMap mW, mB, mW0;
    encode_map(&mW,  wf, 4096);
    encode_map(&mB,  bf, 4096);
    encode_map(&mW0, (const float*)d_in[3], 256);

    cudaFuncSetAttribute(nn_gemm, cudaFuncAttributeMaxDynamicSharedMemorySize, SMEM1);
    cudaFuncSetAttribute(nn_head, cudaFuncAttributeMaxDynamicSharedMemorySize, SMEM2);

    nn_gemm<<<128, 160, SMEM1>>>(mW, mB, mW0, b0);
    nn_head<<<128, 256, SMEM2>>>(stm, W1, b1, W2, b2, W3, b3, out);
}

// round 6
// speedup vs baseline: 2.2929x; 2.2929x over previous
#include <cuda_runtime.h>
#include <cuda.h>
#include <cstdint>

// ---------------- constants ----------------
#define NUMF    41024
#define KHALF   (NUMF / 2)          // 20512 per K-split CTA
#define KCHUNK  32                  // floats per pipeline chunk
#define NCH     (KHALF / KCHUNK)    // 641 exact
#define STAGES  4
#define ASTG    16384               // A: 128 rows x 128B
#define BSTG    32768               // B: 256 rows x 128B
#define STGB    (ASTG + BSTG)       // 49152
#define SMEM1   (2048 + STAGES * STGB)   // 198656

// K-split partial accumulators: [kt][row 0..8191][neuron 0..255]
__device__ float g_part[2][8192 * 256];

// ---------------- device helpers ----------------
__device__ __forceinline__ uint32_t smem_u32(const void* p) {
    uint32_t a;
    asm("{ .reg .u64 t; cvta.to.shared.u64 t, %1; cvt.u32.u64 %0, t; }" : "=r"(a) : "l"(p));
    return a;
}
__device__ __forceinline__ void mbar_init(uint32_t a, uint32_t c) {
    asm volatile("mbarrier.init.shared.b64 [%0], %1;" :: "r"(a), "r"(c) : "memory");
}
__device__ __forceinline__ void mbar_expect_tx(uint32_t a, uint32_t b) {
    asm volatile("mbarrier.arrive.expect_tx.shared.b64 _, [%0], %1;" :: "r"(a), "r"(b) : "memory");
}
__device__ __forceinline__ void mbar_arrive(uint32_t a) {
    asm volatile("mbarrier.arrive.shared.b64 _, [%0];" :: "r"(a) : "memory");
}
__device__ __forceinline__ void mbar_wait(uint32_t mbar, uint32_t parity) {
    asm volatile(
        "{\n\t.reg .pred P;\n\t"
        "LW_%=:\n\t"
        "mbarrier.try_wait.parity.acquire.cta.shared::cta.b64 P, [%0], %1, 0x989680;\n\t"
        "@P bra.uni LD_%=;\n\t"
        "bra.uni LW_%=;\n\t"
        "LD_%=:\n\t}"
        :: "r"(mbar), "r"(parity) : "memory");
}
__device__ __forceinline__ void tma2d(uint32_t dst, const CUtensorMap* m, int x, int y, uint32_t mbar) {
    asm volatile(
        "cp.async.bulk.tensor.2d.shared::cta.global.tile.mbarrier::complete_tx::bytes "
        "[%0], [%1, {%2, %3}], [%4];"
        :: "r"(dst), "l"(m), "r"(x), "r"(y), "r"(mbar) : "memory");
}
__device__ __forceinline__ uint32_t f2tf32(float x) {
    uint32_t r;
    asm("cvt.rna.tf32.f32 %0, %1;" : "=r"(r) : "f"(x));
    return r;
}
__device__ __forceinline__ void mma_tf32(float* c, const uint32_t* a, const uint32_t* b) {
    asm volatile(
        "mma.sync.aligned.m16n8k8.row.col.f32.tf32.tf32.f32 "
        "{%0,%1,%2,%3}, {%4,%5,%6,%7}, {%8,%9}, {%0,%1,%2,%3};"
        : "+f"(c[0]), "+f"(c[1]), "+f"(c[2]), "+f"(c[3])
        : "r"(a[0]), "r"(a[1]), "r"(a[2]), "r"(a[3]), "r"(b[0]), "r"(b[1]));
}

// ---------------- kernel 1: layer-0 GEMM (tf32 mma.sync, K-split) ----------------
// 128 CTAs: bid = mt*2 + kt. mt 0..31 white, 32..63 black. kt = K half.
// CTA tile: 128 (M, feature rows) x 256 (N, all neurons), K range = kt*20512..+20512.
// 288 threads: warps 0-7 consumers (64x64 warp tiles, 2 per SMSP), warp 8 producer.
__global__ void __launch_bounds__(288, 1) nn_gemm(
    const __grid_constant__ CUtensorMap tmW,
    const __grid_constant__ CUtensorMap tmB,
    const __grid_constant__ CUtensorMap tmW0)
{
    extern __shared__ char raw[];
    char* base = (char*)(((uintptr_t)raw + 1023u) & ~(uintptr_t)1023u);
    uint32_t base_u   = smem_u32(base);
    uint32_t mb_full  = base_u;            // STAGES x 8B
    uint32_t mb_empty = base_u + 512;      // STAGES x 8B
    char* tiles       = base + 1024;
    uint32_t tiles_u  = base_u + 1024;

    const int tid  = threadIdx.x;
    const int wid  = tid >> 5;
    const int lane = tid & 31;
    const int bid  = blockIdx.x;
    const int kt   = bid & 1, mt = bid >> 1;
    const int row0 = (mt & 31) * 128;        // feature row within side
    const int kbase = kt * KHALF;
    const CUtensorMap* tmaA = (mt < 32) ? &tmW : &tmB;

    if (tid == 0) {
        for (int s = 0; s < STAGES; s++) {
            mbar_init(mb_full  + s * 8, 1);
            mbar_init(mb_empty + s * 8, 256);   // 256 consumer threads arrive
        }
        asm volatile("fence.proxy.async.shared::cta;" ::: "memory");
    }
    __syncthreads();

    if (wid == 8) {
        // ---------------- producer (lane 0 only) ----------------
        if (lane == 0) {
#define ISSUE(kc_, s_) do {                                          \
            uint32_t mb_ = mb_full + (s_) * 8;                       \
            mbar_expect_tx(mb_, STGB);                               \
            uint32_t t_ = tiles_u + (s_) * STGB;                     \
            int x_ = kbase + (kc_) * KCHUNK;                         \
            tma2d(t_,        tmaA,  x_, row0, mb_);                  \
            tma2d(t_ + ASTG, &tmW0, x_, 0,    mb_);                  \
        } while (0)
            ISSUE(0, 0); ISSUE(1, 1); ISSUE(2, 2); ISSUE(3, 3);
            int s = 0, ep = 0;
            for (int k = STAGES; k < NCH; k++) {
                mbar_wait(mb_empty + s * 8, ep);
                ISSUE(k, s);
                if (++s == STAGES) { s = 0; ep ^= 1; }
            }
#undef ISSUE
        }
    } else {
        // ---------------- consumers ----------------
        const int wm = (wid >> 2) * 64;      // warp M offset (0/64)
        const int wn = (wid & 3) * 64;       // warp N offset (0/64/128/192)
        const int qr = lane >> 2;            // 0..7
        const int qc = lane & 3;             // 0..3

        // Per-lane swizzled byte offsets (within a 128B row) for ks=0..3.
        // Global-k pairing: pair index p(ks,qc) = 8*(qc>>1) + 2*ks + (qc&1);
        // lane loads 8B at byte 8p; SW128 xor term = (row&7)<<4 = qr<<4.
        int offk[4];
        #pragma unroll
        for (int ks = 0; ks < 4; ks++)
            offk[ks] = 8 * (qc & 1) + ((((ks << 4) | ((qc >> 1) << 6))) ^ (qr << 4));

        float c[4][8][4];
        #pragma unroll
        for (int mi = 0; mi < 4; mi++)
            #pragma unroll
            for (int ni = 0; ni < 8; ni++)
                #pragma unroll
                for (int r = 0; r < 4; r++) c[mi][ni][r] = 0.f;

        int s = 0, fp = 0;
        for (int k = 0; k < NCH; k++) {
            mbar_wait(mb_full + s * 8, fp);
            const char* Ast = tiles + s * STGB;
            const char* Bst = Ast + ASTG;

            #pragma unroll
            for (int ks = 0; ks < 4; ks++) {
                uint32_t a[4][4];
                #pragma unroll
                for (int mi = 0; mi < 4; mi++) {
                    const char* pr = Ast + (wm + mi * 16 + qr) * 128 + offk[ks];
                    float2 v0 = *(const float2*)pr;
                    float2 v1 = *(const float2*)(pr + 8 * 128);
                    a[mi][0] = f2tf32(v0.x); a[mi][2] = f2tf32(v0.y);
                    a[mi][1] = f2tf32(v1.x); a[mi][3] = f2tf32(v1.y);
                }
                uint32_t b[8][2];
                #pragma unroll
                for (int ni = 0; ni < 8; ni++) {
                    float2 v = *(const float2*)(Bst + (wn + ni * 8 + qr) * 128 + offk[ks]);
                    b[ni][0] = f2tf32(v.x); b[ni][1] = f2tf32(v.y);
                }
                #pragma unroll
                for (int mi = 0; mi < 4; mi++)
                    #pragma unroll
                    for (int ni = 0; ni < 8; ni++)
                        mma_tf32(c[mi][ni], a[mi], b[ni]);
            }
            mbar_arrive(mb_empty + s * 8);
            if (++s == STAGES) { s = 0; fp ^= 1; }
        }

        // epilogue: write K-split partials
        float* dst = g_part[kt];
        const int rowbase = mt * 128 + wm;
        #pragma unroll
        for (int ni = 0; ni < 8; ni++) {
            const int col = wn + ni * 8 + qc * 2;
            #pragma unroll
            for (int mi = 0; mi < 4; mi++) {
                const int r = rowbase + mi * 16 + qr;
                float2 v0 = { c[mi][ni][0], c[mi][ni][1] };
                float2 v1 = { c[mi][ni][2], c[mi][ni][3] };
                *(float2*)(dst + (size_t)r * 256 + col)       = v0;
                *(float2*)(dst + (size_t)(r + 8) * 256 + col) = v1;
            }
        }
    }
}

// ---------------- kernel 2: combine partials + blend + clip + MLP head ----------------
#define SW1_PITCH 513
#define SW2_PITCH 33
#define SMEM2 ((32*SW1_PITCH + 32*SW2_PITCH + 8*512 + 8*32 + 256) * 4)

__global__ void __launch_bounds__(256) nn_head(
    const float* __restrict__ stm,
    const float* __restrict__ b0,
    const float* __restrict__ W1, const float* __restrict__ b1,
    const float* __restrict__ W2, const float* __restrict__ b2,
    const float* __restrict__ W3, const float* __restrict__ b3,
    float* __restrict__ out)
{
    extern __shared__ float sm[];
    float* sW1 = sm;                               // 32 x 513
    float* sW2 = sW1 + 32 * SW1_PITCH;             // 32 x 33
    float* sl1 = sW2 + 32 * SW2_PITCH;             // 8 warps x 512
    float* sl2 = sl1 + 8 * 512;                    // 8 warps x 32
    float* sb0 = sl2 + 8 * 32;                     // 256

    int tid = threadIdx.x;
    for (int i = tid; i < 32 * 512; i += 256) sW1[(i >> 9) * SW1_PITCH + (i & 511)] = W1[i];
    for (int i = tid; i < 32 * 32;  i += 256) sW2[(i >> 5) * SW2_PITCH + (i & 31)]  = W2[i];
    if (tid < 256) sb0[tid] = b0[tid];
    __syncthreads();

    int w = tid >> 5, j = tid & 31;
    float* l1 = sl1 + w * 512;
    float* l2 = sl2 + w * 32;
    float bj1 = b1[j], bj2 = b2[j], w3j = W3[j], b3v = b3[0];

    for (int q = 0; q < 4; q++) {
        int b = blockIdx.x * 32 + w * 4 + q;
        const float* p0w = g_part[0] + (size_t)b * 256;
        const float* p1w = g_part[1] + (size_t)b * 256;
        const float* p0b = g_part[0] + (size_t)(4096 + b) * 256;
        const float* p1b = g_part[1] + (size_t)(4096 + b) * 256;
        float s = stm[b];
        for (int t = j; t < 256; t += 32) {
            float wv = p0w[t] + p1w[t] + sb0[t];
            float bv = p0b[t] + p1b[t] + sb0[t];
            float x0 = s * wv + (1.f - s) * bv;
            float x1 = s * bv + (1.f - s) * wv;
            l1[t]       = fminf(fmaxf(x0, 0.f), 1.f);
            l1[256 + t] = fminf(fmaxf(x1, 0.f), 1.f);
        }
        __syncwarp();
        float a2 = bj1;
        const float* wr = sW1 + j * SW1_PITCH;
        #pragma unroll 8
        for (int k = 0; k < 512; k++) a2 += wr[k] * l1[k];
        a2 = fminf(fmaxf(a2, 0.f), 1.f);
        l2[j] = a2;
        __syncwarp();
        float a3 = bj2;
        const float* wr2 = sW2 + j * SW2_PITCH;
        #pragma unroll
        for (int k = 0; k < 32; k++) a3 += wr2[k] * l2[k];
        a3 = fminf(fmaxf(a3, 0.f), 1.f);
        float v = w3j * a3;
        #pragma unroll
        for (int o = 16; o > 0; o >>= 1) v += __shfl_xor_sync(0xffffffffu, v, o);
        if (j == 0) out[b] = v + b3v;
        __syncwarp();
    }
}

// ---------------- host ----------------
typedef CUresult (*EncodeFn)(CUtensorMap*, CUtensorMapDataType, cuuint32_t, void*,
                             const cuuint64_t*, const cuuint64_t*, const cuuint32_t*, const cuuint32_t*,
                             CUtensorMapInterleave, CUtensorMapSwizzle,
                             CUtensorMapL2promotion, CUtensorMapFloatOOBfill);

static void encode_map(CUtensorMap* m, const void* ptr, unsigned long long rows, unsigned box_rows) {
    void* p = nullptr;
    cudaDriverEntryPointQueryResult qr;
    cudaGetDriverEntryPointByVersion("cuTensorMapEncodeTiled", &p, 12000, cudaEnableDefault, &qr);
    EncodeFn fn = (EncodeFn)p;
    cuuint64_t dims[2]    = { (cuuint64_t)NUMF, (cuuint64_t)rows };
    cuuint64_t strides[1] = { (cuuint64_t)NUMF * 4ull };
    cuuint32_t box[2]     = { 32u, box_rows };   // 128B x box_rows, SW128
    cuuint32_t es[2]      = { 1u, 1u };
    fn(m, CU_TENSOR_MAP_DATA_TYPE_FLOAT32, 2, (void*)ptr, dims, strides, box, es,
       CU_TENSOR_MAP_INTERLEAVE_NONE, CU_TENSOR_MAP_SWIZZLE_128B,
       CU_TENSOR_MAP_L2_PROMOTION_L2_128B, CU_TENSOR_MAP_FLOAT_OOB_FILL_NONE);
}

extern "C" void kernel_launch(void* const* d_in, const int* in_sizes, int n_in,
                              void* d_out, int out_size) {
    const float* wf  = (const float*)d_in[0];
    const float* bf  = (const float*)d_in[1];
    const float* stm = (const float*)d_in[2];
    const float* W0  = (const float*)d_in[3];
    const float* b0  = (const float*)d_in[4];
    const float* W1  = (const float*)d_in[5];
    const float* b1  = (const float*)d_in[6];
    const float* W2  = (const float*)d_in[7];
    const float* b2  = (const float*)d_in[8];
    const float* W3  = (const float*)d_in[9];
    const float* b3  = (const float*)d_in[10];
    float* out = (float*)d_out;

    CUtensorMap mW, mB, mW0;
    encode_map(&mW,  wf, 4096, 128);
    encode_map(&mB,  bf, 4096, 128);
    encode_map(&mW0, W0, 256,  256);

    cudaFuncSetAttribute(nn_gemm, cudaFuncAttributeMaxDynamicSharedMemorySize, SMEM1);
    cudaFuncSetAttribute(nn_head, cudaFuncAttributeMaxDynamicSharedMemorySize, SMEM2);

    nn_gemm<<<128, 288, SMEM1>>>(mW, mB, mW0);
    nn_head<<<128, 256, SMEM2>>>(stm, b0, W1, b1, W2, b2, W3, b3, out);
}

// round 7
// speedup vs baseline: 4.8271x; 2.1053x over previous
#include <cuda_runtime.h>
#include <cuda.h>
#include <cstdint>

// ---------------- constants ----------------
#define NUMF    41024
#define KHALF   (NUMF / 2)          // 20512 per K-split CTA
#define KCHUNK  32                  // floats per pipeline chunk (= 2 k16 mma steps)
#define NCH     (KHALF / KCHUNK)    // 641 exact
#define STAGES  4
#define ASTG    16384               // A: 128 rows x 128B
#define BSTG    32768               // B: 256 rows x 128B
#define STGB    (ASTG + BSTG)       // 49152
#define SMEM1   (2048 + STAGES * STGB)   // 198656

// K-split partial accumulators: [kt][row 0..8191][neuron 0..255]
__device__ float g_part[2][8192 * 256];

// ---------------- device helpers ----------------
__device__ __forceinline__ uint32_t smem_u32(const void* p) {
    uint32_t a;
    asm("{ .reg .u64 t; cvta.to.shared.u64 t, %1; cvt.u32.u64 %0, t; }" : "=r"(a) : "l"(p));
    return a;
}
__device__ __forceinline__ void mbar_init(uint32_t a, uint32_t c) {
    asm volatile("mbarrier.init.shared.b64 [%0], %1;" :: "r"(a), "r"(c) : "memory");
}
__device__ __forceinline__ void mbar_expect_tx(uint32_t a, uint32_t b) {
    asm volatile("mbarrier.arrive.expect_tx.shared.b64 _, [%0], %1;" :: "r"(a), "r"(b) : "memory");
}
__device__ __forceinline__ void mbar_arrive(uint32_t a) {
    asm volatile("mbarrier.arrive.shared.b64 _, [%0];" :: "r"(a) : "memory");
}
__device__ __forceinline__ void mbar_wait(uint32_t mbar, uint32_t parity) {
    asm volatile(
        "{\n\t.reg .pred P;\n\t"
        "LW_%=:\n\t"
        "mbarrier.try_wait.parity.acquire.cta.shared::cta.b64 P, [%0], %1, 0x989680;\n\t"
        "@P bra.uni LD_%=;\n\t"
        "bra.uni LW_%=;\n\t"
        "LD_%=:\n\t}"
        :: "r"(mbar), "r"(parity) : "memory");
}
__device__ __forceinline__ void tma2d(uint32_t dst, const CUtensorMap* m, int x, int y, uint32_t mbar) {
    asm volatile(
        "cp.async.bulk.tensor.2d.shared::cta.global.tile.mbarrier::complete_tx::bytes "
        "[%0], [%1, {%2, %3}], [%4];"
        :: "r"(dst), "l"(m), "r"(x), "r"(y), "r"(mbar) : "memory");
}
// pack two fp32 -> f16x2 {lo, hi}
__device__ __forceinline__ uint32_t f2h2(float lo, float hi) {
    uint32_t r;
    asm("cvt.rn.f16x2.f32 %0, %2, %1;" : "=r"(r) : "f"(lo), "f"(hi));
    return r;
}
__device__ __forceinline__ void mma_f16(float* c, const uint32_t* a, const uint32_t* b) {
    asm volatile(
        "mma.sync.aligned.m16n8k16.row.col.f32.f16.f16.f32 "
        "{%0,%1,%2,%3}, {%4,%5,%6,%7}, {%8,%9}, {%0,%1,%2,%3};"
        : "+f"(c[0]), "+f"(c[1]), "+f"(c[2]), "+f"(c[3])
        : "r"(a[0]), "r"(a[1]), "r"(a[2]), "r"(a[3]), "r"(b[0]), "r"(b[1]));
}

// ---------------- kernel 1: layer-0 GEMM (fp16 mma.sync, fp32 accum, K-split) ----------------
// 128 CTAs: bid = mt*2 + kt. mt 0..31 white, 32..63 black. kt = K half.
// CTA tile: 128 (M) x 256 (N), K range = kt*20512..+20512.
// 288 threads: warps 0-7 consumers (64x64 warp tiles), warp 8 producer.
__global__ void __launch_bounds__(288, 1) nn_gemm(
    const __grid_constant__ CUtensorMap tmW,
    const __grid_constant__ CUtensorMap tmB,
    const __grid_constant__ CUtensorMap tmW0)
{
    extern __shared__ char raw[];
    char* base = (char*)(((uintptr_t)raw + 1023u) & ~(uintptr_t)1023u);
    uint32_t base_u   = smem_u32(base);
    uint32_t mb_full  = base_u;            // STAGES x 8B
    uint32_t mb_empty = base_u + 512;      // STAGES x 8B
    char* tiles       = base + 1024;
    uint32_t tiles_u  = base_u + 1024;

    const int tid  = threadIdx.x;
    const int wid  = tid >> 5;
    const int lane = tid & 31;
    const int bid  = blockIdx.x;
    const int kt   = bid & 1, mt = bid >> 1;
    const int row0 = (mt & 31) * 128;        // feature row within side
    const int kbase = kt * KHALF;
    const CUtensorMap* tmaA = (mt < 32) ? &tmW : &tmB;

    if (tid == 0) {
        for (int s = 0; s < STAGES; s++) {
            mbar_init(mb_full  + s * 8, 1);
            mbar_init(mb_empty + s * 8, 256);
        }
        asm volatile("fence.proxy.async.shared::cta;" ::: "memory");
    }
    __syncthreads();

    if (wid == 8) {
        if (lane == 0) {
#define ISSUE(kc_, s_) do {                                          \
            uint32_t mb_ = mb_full + (s_) * 8;                       \
            mbar_expect_tx(mb_, STGB);                               \
            uint32_t t_ = tiles_u + (s_) * STGB;                     \
            int x_ = kbase + (kc_) * KCHUNK;                         \
            tma2d(t_,        tmaA,  x_, row0, mb_);                  \
            tma2d(t_ + ASTG, &tmW0, x_, 0,    mb_);                  \
        } while (0)
            ISSUE(0, 0); ISSUE(1, 1); ISSUE(2, 2); ISSUE(3, 3);
            int s = 0, ep = 0;
            for (int k = STAGES; k < NCH; k++) {
                mbar_wait(mb_empty + s * 8, ep);
                ISSUE(k, s);
                if (++s == STAGES) { s = 0; ep ^= 1; }
            }
#undef ISSUE
        }
    } else {
        // ---------------- consumers ----------------
        const int wm = (wid >> 2) * 64;      // warp M offset (0/64)
        const int wn = (wid & 3) * 64;       // warp N offset (0/64/128/192)
        const int g  = lane >> 2;            // 0..7
        const int t  = lane & 3;             // 0..3

        // Global-k pair index within 32-float chunk: p(s,h,t) = 4s + 2h + (t&1) + 8(t>>1)
        // swizzled byte offset within 128B row: (8p) ^ (g<<4)   (rows used have row&7 == g)
        int off[2][2];
        #pragma unroll
        for (int s_ = 0; s_ < 2; s_++)
            #pragma unroll
            for (int h_ = 0; h_ < 2; h_++)
                off[s_][h_] = ((32 * s_ + 16 * h_ + 8 * (t & 1) + 64 * (t >> 1)) ^ (g << 4));

        float c[4][8][4];
        #pragma unroll
        for (int mi = 0; mi < 4; mi++)
            #pragma unroll
            for (int ni = 0; ni < 8; ni++)
                #pragma unroll
                for (int r = 0; r < 4; r++) c[mi][ni][r] = 0.f;

        int s = 0, fp = 0;
        for (int k = 0; k < NCH; k++) {
            mbar_wait(mb_full + s * 8, fp);
            const char* Ast = tiles + s * STGB;
            const char* Bst = Ast + ASTG;

            #pragma unroll
            for (int st = 0; st < 2; st++) {
                uint32_t a[4][4];
                #pragma unroll
                for (int mi = 0; mi < 4; mi++) {
                    const char* pr = Ast + (wm + mi * 16 + g) * 128;
                    float2 v00 = *(const float2*)(pr + off[st][0]);           // row g,   k[0:8)
                    float2 v10 = *(const float2*)(pr + 1024 + off[st][0]);    // row g+8, k[0:8)
                    float2 v01 = *(const float2*)(pr + off[st][1]);           // row g,   k[8:16)
                    float2 v11 = *(const float2*)(pr + 1024 + off[st][1]);    // row g+8, k[8:16)
                    a[mi][0] = f2h2(v00.x, v00.y);
                    a[mi][1] = f2h2(v10.x, v10.y);
                    a[mi][2] = f2h2(v01.x, v01.y);
                    a[mi][3] = f2h2(v11.x, v11.y);
                }
                uint32_t b[8][2];
                #pragma unroll
                for (int ni = 0; ni < 8; ni++) {
                    const char* pr = Bst + (wn + ni * 8 + g) * 128;
                    float2 u0 = *(const float2*)(pr + off[st][0]);
                    float2 u1 = *(const float2*)(pr + off[st][1]);
                    b[ni][0] = f2h2(u0.x, u0.y);
                    b[ni][1] = f2h2(u1.x, u1.y);
                }
                #pragma unroll
                for (int mi = 0; mi < 4; mi++)
                    #pragma unroll
                    for (int ni = 0; ni < 8; ni++)
                        mma_f16(c[mi][ni], a[mi], b[ni]);
            }
            mbar_arrive(mb_empty + s * 8);
            if (++s == STAGES) { s = 0; fp ^= 1; }
        }

        // epilogue: write K-split partials
        float* dst = g_part[kt];
        const int rowbase = mt * 128 + wm;
        #pragma unroll
        for (int ni = 0; ni < 8; ni++) {
            const int col = wn + ni * 8 + (t << 1);
            #pragma unroll
            for (int mi = 0; mi < 4; mi++) {
                const int r = rowbase + mi * 16 + g;
                float2 v0 = { c[mi][ni][0], c[mi][ni][1] };
                float2 v1 = { c[mi][ni][2], c[mi][ni][3] };
                *(float2*)(dst + (size_t)r * 256 + col)       = v0;
                *(float2*)(dst + (size_t)(r + 8) * 256 + col) = v1;
            }
        }
    }
}

// ---------------- kernel 2: combine partials + blend + clip + MLP head ----------------
#define SW1_PITCH 513
#define SW2_PITCH 33
#define SMEM2 ((32*SW1_PITCH + 32*SW2_PITCH + 8*512 + 8*32 + 256) * 4)

__global__ void __launch_bounds__(256) nn_head(
    const float* __restrict__ stm,
    const float* __restrict__ b0,
    const float* __restrict__ W1, const float* __restrict__ b1,
    const float* __restrict__ W2, const float* __restrict__ b2,
    const float* __restrict__ W3, const float* __restrict__ b3,
    float* __restrict__ out)
{
    extern __shared__ float sm[];
    float* sW1 = sm;                               // 32 x 513
    float* sW2 = sW1 + 32 * SW1_PITCH;             // 32 x 33
    float* sl1 = sW2 + 32 * SW2_PITCH;             // 8 warps x 512
    float* sl2 = sl1 + 8 * 512;                    // 8 warps x 32
    float* sb0 = sl2 + 8 * 32;                     // 256

    int tid = threadIdx.x;
    for (int i = tid; i < 32 * 512; i += 256) sW1[(i >> 9) * SW1_PITCH + (i & 511)] = W1[i];
    for (int i = tid; i < 32 * 32;  i += 256) sW2[(i >> 5) * SW2_PITCH + (i & 31)]  = W2[i];
    if (tid < 256) sb0[tid] = b0[tid];
    __syncthreads();

    int w = tid >> 5, j = tid & 31;
    float* l1 = sl1 + w * 512;
    float* l2 = sl2 + w * 32;
    float bj1 = b1[j], bj2 = b2[j], w3j = W3[j], b3v = b3[0];

    for (int q = 0; q < 2; q++) {
        int b = blockIdx.x * 16 + w * 2 + q;
        const float* p0w = g_part[0] + (size_t)b * 256;
        const float* p1w = g_part[1] + (size_t)b * 256;
        const float* p0b = g_part[0] + (size_t)(4096 + b) * 256;
        const float* p1b = g_part[1] + (size_t)(4096 + b) * 256;
        float s = stm[b];
        for (int tt = j; tt < 256; tt += 32) {
            float wv = p0w[tt] + p1w[tt] + sb0[tt];
            float bv = p0b[tt] + p1b[tt] + sb0[tt];
            float x0 = s * wv + (1.f - s) * bv;
            float x1 = s * bv + (1.f - s) * wv;
            l1[tt]       = fminf(fmaxf(x0, 0.f), 1.f);
            l1[256 + tt] = fminf(fmaxf(x1, 0.f), 1.f);
        }
        __syncwarp();
        float a2 = bj1;
        const float* wr = sW1 + j * SW1_PITCH;
        #pragma unroll 8
        for (int k = 0; k < 512; k++) a2 += wr[k] * l1[k];
        a2 = fminf(fmaxf(a2, 0.f), 1.f);
        l2[j] = a2;
        __syncwarp();
        float a3 = bj2;
        const float* wr2 = sW2 + j * SW2_PITCH;
        #pragma unroll
        for (int k = 0; k < 32; k++) a3 += wr2[k] * l2[k];
        a3 = fminf(fmaxf(a3, 0.f), 1.f);
        float v = w3j * a3;
        #pragma unroll
        for (int o = 16; o > 0; o >>= 1) v += __shfl_xor_sync(0xffffffffu, v, o);
        if (j == 0) out[b] = v + b3v;
        __syncwarp();
    }
}

// ---------------- host ----------------
typedef CUresult (*EncodeFn)(CUtensorMap*, CUtensorMapDataType, cuuint32_t, void*,
                             const cuuint64_t*, const cuuint64_t*, const cuuint32_t*, const cuuint32_t*,
                             CUtensorMapInterleave, CUtensorMapSwizzle,
                             CUtensorMapL2promotion, CUtensorMapFloatOOBfill);

static void encode_map(CUtensorMap* m, const void* ptr, unsigned long long rows, unsigned box_rows) {
    void* p = nullptr;
    cudaDriverEntryPointQueryResult qr;
    cudaGetDriverEntryPointByVersion("cuTensorMapEncodeTiled", &p, 12000, cudaEnableDefault, &qr);
    EncodeFn fn = (EncodeFn)p;
    cuuint64_t dims[2]    = { (cuuint64_t)NUMF, (cuuint64_t)rows };
    cuuint64_t strides[1] = { (cuuint64_t)NUMF * 4ull };
    cuuint32_t box[2]     = { 32u, box_rows };   // 128B x box_rows, SW128
    cuuint32_t es[2]      = { 1u, 1u };
    fn(m, CU_TENSOR_MAP_DATA_TYPE_FLOAT32, 2, (void*)ptr, dims, strides, box, es,
       CU_TENSOR_MAP_INTERLEAVE_NONE, CU_TENSOR_MAP_SWIZZLE_128B,
       CU_TENSOR_MAP_L2_PROMOTION_L2_128B, CU_TENSOR_MAP_FLOAT_OOB_FILL_NONE);
}

extern "C" void kernel_launch(void* const* d_in, const int* in_sizes, int n_in,
                              void* d_out, int out_size) {
    const float* wf  = (const float*)d_in[0];
    const float* bf  = (const float*)d_in[1];
    const float* stm = (const float*)d_in[2];
    const float* W0  = (const float*)d_in[3];
    const float* b0  = (const float*)d_in[4];
    const float* W1  = (const float*)d_in[5];
    const float* b1  = (const float*)d_in[6];
    const float* W2  = (const float*)d_in[7];
    const float* b2  = (const float*)d_in[8];
    const float* W3  = (const float*)d_in[9];
    const float* b3  = (const float*)d_in[10];
    float* out = (float*)d_out;

    CUtensorMap mW, mB, mW0;
    encode_map(&mW,  wf, 4096, 128);
    encode_map(&mB,  bf, 4096, 128);
    encode_map(&mW0, W0, 256,  256);

    cudaFuncSetAttribute(nn_gemm, cudaFuncAttributeMaxDynamicSharedMemorySize, SMEM1);
    cudaFuncSetAttribute(nn_head, cudaFuncAttributeMaxDynamicSharedMemorySize, SMEM2);

    nn_gemm<<<128, 288, SMEM1>>>(mW, mB, mW0);
    nn_head<<<256, 256, SMEM2>>>(stm, b0, W1, b1, W2, b2, W3, b3, out);
}

// round 10
// speedup vs baseline: 5.4871x; 1.1367x over previous
#include <cuda_runtime.h>
#include <cuda.h>
#include <cstdint>

// ---------------- constants ----------------
#define NUMF    41024
#define KCHUNK  32                  // floats per pipeline chunk (= 2 k16 mma steps)
#define CHPM    1282                // chunks per M-tile (41024/32)
#define NMT     64                  // M-tiles (32 white + 32 black)
#define TOTC    (NMT * CHPM)        // 82048 total chunk-columns
#define GRID1   148                 // one CTA per SM
#define STAGES  4
#define ASTG    16384               // A: 128 rows x 128B
#define BSTG    32768               // B: 256 rows x 128B
#define STGB    (ASTG + BSTG)       // 49152
#define SMEM1   (2048 + STAGES * STGB)   // 198656

// per-CTA partials: [cta][part 0/1][128 rows x 256 neurons]
__device__ float g_part[GRID1][2][128 * 256];

// ---------------- device helpers ----------------
__device__ __forceinline__ uint32_t smem_u32(const void* p) {
    uint32_t a;
    asm("{ .reg .u64 t; cvta.to.shared.u64 t, %1; cvt.u32.u64 %0, t; }" : "=r"(a) : "l"(p));
    return a;
}
__device__ __forceinline__ void mbar_init(uint32_t a, uint32_t c) {
    asm volatile("mbarrier.init.shared.b64 [%0], %1;" :: "r"(a), "r"(c) : "memory");
}
__device__ __forceinline__ void mbar_expect_tx(uint32_t a, uint32_t b) {
    asm volatile("mbarrier.arrive.expect_tx.shared.b64 _, [%0], %1;" :: "r"(a), "r"(b) : "memory");
}
__device__ __forceinline__ void mbar_arrive(uint32_t a) {
    asm volatile("mbarrier.arrive.shared.b64 _, [%0];" :: "r"(a) : "memory");
}
__device__ __forceinline__ void mbar_wait(uint32_t mbar, uint32_t parity) {
    asm volatile(
        "{\n\t.reg .pred P;\n\t"
        "LW_%=:\n\t"
        "mbarrier.try_wait.parity.acquire.cta.shared::cta.b64 P, [%0], %1, 0x989680;\n\t"
        "@P bra.uni LD_%=;\n\t"
        "bra.uni LW_%=;\n\t"
        "LD_%=:\n\t}"
        :: "r"(mbar), "r"(parity) : "memory");
}
__device__ __forceinline__ void tma2d(uint32_t dst, const CUtensorMap* m, int x, int y, uint32_t mbar) {
    asm volatile(
        "cp.async.bulk.tensor.2d.shared::cta.global.tile.mbarrier::complete_tx::bytes "
        "[%0], [%1, {%2, %3}], [%4];"
        :: "r"(dst), "l"(m), "r"(x), "r"(y), "r"(mbar) : "memory");
}
// pack two fp32 -> f16x2 {lo, hi}
__device__ __forceinline__ uint32_t f2h2(float lo, float hi) {
    uint32_t r;
    asm("cvt.rn.f16x2.f32 %0, %2, %1;" : "=r"(r) : "f"(lo), "f"(hi));
    return r;
}
__device__ __forceinline__ void mma_f16(float* c, const uint32_t* a, const uint32_t* b) {
    asm volatile(
        "mma.sync.aligned.m16n8k16.row.col.f32.f16.f16.f32 "
        "{%0,%1,%2,%3}, {%4,%5,%6,%7}, {%8,%9}, {%0,%1,%2,%3};"
        : "+f"(c[0]), "+f"(c[1]), "+f"(c[2]), "+f"(c[3])
        : "r"(a[0]), "r"(a[1]), "r"(a[2]), "r"(a[3]), "r"(b[0]), "r"(b[1]));
}

// ---------------- kernel 1: layer-0 GEMM (fp16 mma.sync, balanced 148-CTA split) ----------------
// CTA i owns chunk-columns [i*TOTC/148, (i+1)*TOTC/148) of the linearized
// (M-tile, K-chunk) space. A range spans at most 2 M-tiles; partial tiles are
// flushed to g_part[i][part]. 288 threads: warps 0-7 consumers, warp 8 producer.
__global__ void __launch_bounds__(288, 1) nn_gemm(
    const __grid_constant__ CUtensorMap tmW,
    const __grid_constant__ CUtensorMap tmB,
    const __grid_constant__ CUtensorMap tmW0)
{
    extern __shared__ char raw[];
    char* base = (char*)(((uintptr_t)raw + 1023u) & ~(uintptr_t)1023u);
    uint32_t base_u   = smem_u32(base);
    uint32_t mb_full  = base_u;            // STAGES x 8B
    uint32_t mb_empty = base_u + 512;      // STAGES x 8B
    char* tiles       = base + 1024;
    uint32_t tiles_u  = base_u + 1024;

    const int tid  = threadIdx.x;
    const int wid  = tid >> 5;
    const int lane = tid & 31;
    const int bid  = blockIdx.x;

    const int cs = (int)((long long)bid * TOTC / GRID1);        // start chunk
    const int ce = (int)((long long)(bid + 1) * TOTC / GRID1);  // end chunk
    const int nc = ce - cs;                                     // 554 or 555
    const int mt0 = cs / CHPM;
    const int mt1 = (ce - 1) / CHPM;                            // mt0 or mt0+1

    if (tid == 0) {
        for (int s = 0; s < STAGES; s++) {
            mbar_init(mb_full  + s * 8, 1);
            mbar_init(mb_empty + s * 8, 256);
        }
        asm volatile("fence.proxy.async.shared::cta;" ::: "memory");
    }
    __syncthreads();

    if (wid == 8) {
        if (lane == 0) {
            // ---------------- producer ----------------
#define ISSUE(c_, s_) do {                                           \
            int mt_ = (c_) / CHPM;                                   \
            int kc_ = (c_) - mt_ * CHPM;                             \
            const CUtensorMap* mp_ = (mt_ < 32) ? &tmW : &tmB;       \
            uint32_t mb_ = mb_full + (s_) * 8;                       \
            mbar_expect_tx(mb_, STGB);                               \
            uint32_t t_ = tiles_u + (s_) * STGB;                     \
            tma2d(t_,        mp_,   kc_ * KCHUNK, (mt_ & 31) * 128, mb_); \
            tma2d(t_ + ASTG, &tmW0, kc_ * KCHUNK, 0,                mb_); \
        } while (0)
            ISSUE(cs, 0); ISSUE(cs + 1, 1); ISSUE(cs + 2, 2); ISSUE(cs + 3, 3);
            int s = 0, ep = 0;
            for (int j = STAGES; j < nc; j++) {
                mbar_wait(mb_empty + s * 8, ep);
                ISSUE(cs + j, s);
                if (++s == STAGES) { s = 0; ep ^= 1; }
            }
#undef ISSUE
        }
    } else {
        // ---------------- consumers ----------------
        const int wm = (wid >> 2) * 64;      // warp M offset (0/64)
        const int wn = (wid & 3) * 64;       // warp N offset (0/64/128/192)
        const int g  = lane >> 2;            // 0..7
        const int t  = lane & 3;             // 0..3

        // conflict-free swizzled byte offsets (validated in R7)
        int off[2][2];
        #pragma unroll
        for (int s_ = 0; s_ < 2; s_++)
            #pragma unroll
            for (int h_ = 0; h_ < 2; h_++)
                off[s_][h_] = ((32 * s_ + 16 * h_ + 8 * (t & 1) + 64 * (t >> 1)) ^ (g << 4));

        float c[4][8][4];
        #pragma unroll
        for (int mi = 0; mi < 4; mi++)
            #pragma unroll
            for (int ni = 0; ni < 8; ni++)
                #pragma unroll
                for (int r = 0; r < 4; r++) c[mi][ni][r] = 0.f;

        // local index of the last chunk of part 0 (or -1 if single part)
        const int jb = (mt1 > mt0) ? ((mt0 + 1) * CHPM - 1 - cs) : -1;

        int s = 0, fp = 0;
        for (int j = 0; j < nc; j++) {
            mbar_wait(mb_full + s * 8, fp);
            const char* Ast = tiles + s * STGB;
            const char* Bst = Ast + ASTG;

            #pragma unroll
            for (int st = 0; st < 2; st++) {
                uint32_t a[4][4];
                #pragma unroll
                for (int mi = 0; mi < 4; mi++) {
                    const char* pr = Ast + (wm + mi * 16 + g) * 128;
                    float2 v00 = *(const float2*)(pr + off[st][0]);
                    float2 v10 = *(const float2*)(pr + 1024 + off[st][0]);
                    float2 v01 = *(const float2*)(pr + off[st][1]);
                    float2 v11 = *(const float2*)(pr + 1024 + off[st][1]);
                    a[mi][0] = f2h2(v00.x, v00.y);
                    a[mi][1] = f2h2(v10.x, v10.y);
                    a[mi][2] = f2h2(v01.x, v01.y);
                    a[mi][3] = f2h2(v11.x, v11.y);
                }
                uint32_t b[8][2];
                #pragma unroll
                for (int ni = 0; ni < 8; ni++) {
                    const char* pr = Bst + (wn + ni * 8 + g) * 128;
                    float2 u0 = *(const float2*)(pr + off[st][0]);
                    float2 u1 = *(const float2*)(pr + off[st][1]);
                    b[ni][0] = f2h2(u0.x, u0.y);
                    b[ni][1] = f2h2(u1.x, u1.y);
                }
                #pragma unroll
                for (int mi = 0; mi < 4; mi++)
                    #pragma unroll
                    for (int ni = 0; ni < 8; ni++)
                        mma_f16(c[mi][ni], a[mi], b[ni]);
            }
            mbar_arrive(mb_empty + s * 8);
            if (++s == STAGES) { s = 0; fp ^= 1; }

            if (j == jb) {
                // flush part 0, reset accumulators
                float* dst = g_part[bid][0];
                #pragma unroll
                for (int ni = 0; ni < 8; ni++) {
                    const int col = wn + ni * 8 + (t << 1);
                    #pragma unroll
                    for (int mi = 0; mi < 4; mi++) {
                        const int r = wm + mi * 16 + g;
                        *(float2*)(dst + (size_t)r * 256 + col)       = make_float2(c[mi][ni][0], c[mi][ni][1]);
                        *(float2*)(dst + (size_t)(r + 8) * 256 + col) = make_float2(c[mi][ni][2], c[mi][ni][3]);
                        c[mi][ni][0] = c[mi][ni][1] = c[mi][ni][2] = c[mi][ni][3] = 0.f;
                    }
                }
            }
        }

        // final flush (part 1 if two parts, else part 0)
        {
            float* dst = g_part[bid][(mt1 > mt0) ? 1 : 0];
            #pragma unroll
            for (int ni = 0; ni < 8; ni++) {
                const int col = wn + ni * 8 + (t << 1);
                #pragma unroll
                for (int mi = 0; mi < 4; mi++) {
                    const int r = wm + mi * 16 + g;
                    *(float2*)(dst + (size_t)r * 256 + col)       = make_float2(c[mi][ni][0], c[mi][ni][1]);
                    *(float2*)(dst + (size_t)(r + 8) * 256 + col) = make_float2(c[mi][ni][2], c[mi][ni][3]);
                }
            }
        }
    }
}

// ---------------- kernel 2: gather partials + blend + clip + MLP head ----------------
#define SW1_PITCH 513
#define SW2_PITCH 33
#define SMEM2 ((32*SW1_PITCH + 32*SW2_PITCH + 8*512 + 8*32 + 256) * 4)

// CTA containing chunk c: largest i with floor(i*TOTC/GRID1) <= c,
// i.e. i = floor(((c+1)*GRID1 - 1) / TOTC).
__device__ __forceinline__ int cover_cta(int c) {
    return (int)(((long long)(c + 1) * GRID1 - 1) / TOTC);
}
// gather the (up to 4) partial-tile pointers covering M-tile mt
__device__ __forceinline__ int gather_parts(int mt, const float** ptr) {
    int c0 = mt * CHPM;
    int iA = cover_cta(c0);
    int iB = cover_cta(c0 + CHPM - 1);
    int n = 0;
    for (int i = iA; i <= iB && n < 4; i++) {
        int si = (int)((long long)i * TOTC / GRID1);
        int slot = (si / CHPM == mt) ? 0 : 1;   // CTA started in this mt -> its part 0
        ptr[n++] = g_part[i][slot];
    }
    return n;
}

__global__ void __launch_bounds__(256) nn_head(
    const float* __restrict__ stm,
    const float* __restrict__ b0,
    const float* __restrict__ W1, const float* __restrict__ b1,
    const float* __restrict__ W2, const float* __restrict__ b2,
    const float* __restrict__ W3, const float* __restrict__ b3,
    float* __restrict__ out)
{
    extern __shared__ float sm[];
    float* sW1 = sm;                               // 32 x 513
    float* sW2 = sW1 + 32 * SW1_PITCH;             // 32 x 33
    float* sl1 = sW2 + 32 * SW2_PITCH;             // 8 warps x 512
    float* sl2 = sl1 + 8 * 512;                    // 8 warps x 32
    float* sb0 = sl2 + 8 * 32;                     // 256

    int tid = threadIdx.x;
    for (int i = tid; i < 32 * 512; i += 256) sW1[(i >> 9) * SW1_PITCH + (i & 511)] = W1[i];
    for (int i = tid; i < 32 * 32;  i += 256) sW2[(i >> 5) * SW2_PITCH + (i & 31)]  = W2[i];
    if (tid < 256) sb0[tid] = b0[tid];
    __syncthreads();

    int w = tid >> 5, j = tid & 31;
    float* l1 = sl1 + w * 512;
    float* l2 = sl2 + w * 32;
    float bj1 = b1[j], bj2 = b2[j], w3j = W3[j], b3v = b3[0];

    for (int q = 0; q < 2; q++) {
        int b = blockIdx.x * 16 + w * 2 + q;
        const int lr = (b & 127) * 256;      // local row offset within partial tile
        const float* pw[4];
        const float* pb[4];
        int nw_ = gather_parts(b >> 7, pw);
        int nb_ = gather_parts(32 + (b >> 7), pb);
        float s = stm[b];
        for (int tt = j; tt < 256; tt += 32) {
            float wv = sb0[tt];
            for (int k = 0; k < nw_; k++) wv += pw[k][lr + tt];
            float bv = sb0[tt];
            for (int k = 0; k < nb_; k++) bv += pb[k][lr + tt];
            float x0 = s * wv + (1.f - s) * bv;
            float x1 = s * bv + (1.f - s) * wv;
            l1[tt]       = fminf(fmaxf(x0, 0.f), 1.f);
            l1[256 + tt] = fminf(fmaxf(x1, 0.f), 1.f);
        }
        __syncwarp();
        float a2 = bj1;
        const float* wr = sW1 + j * SW1_PITCH;
        #pragma unroll 8
        for (int k = 0; k < 512; k++) a2 += wr[k] * l1[k];
        a2 = fminf(fmaxf(a2, 0.f), 1.f);
        l2[j] = a2;
        __syncwarp();
        float a3 = bj2;
        const float* wr2 = sW2 + j * SW2_PITCH;
        #pragma unroll
        for (int k = 0; k < 32; k++) a3 += wr2[k] * l2[k];
        a3 = fminf(fmaxf(a3, 0.f), 1.f);
        float v = w3j * a3;
        #pragma unroll
        for (int o = 16; o > 0; o >>= 1) v += __shfl_xor_sync(0xffffffffu, v, o);
        if (j == 0) out[b] = v + b3v;
        __syncwarp();
    }
}

// ---------------- host ----------------
typedef CUresult (*EncodeFn)(CUtensorMap*, CUtensorMapDataType, cuuint32_t, void*,
                             const cuuint64_t*, const cuuint64_t*, const cuuint32_t*, const cuuint32_t*,
                             CUtensorMapInterleave, CUtensorMapSwizzle,
                             CUtensorMapL2promotion, CUtensorMapFloatOOBfill);

static void encode_map(CUtensorMap* m, const void* ptr, unsigned long long rows, unsigned box_rows) {
    void* p = nullptr;
    cudaDriverEntryPointQueryResult qr;
    cudaGetDriverEntryPointByVersion("cuTensorMapEncodeTiled", &p, 12000, cudaEnableDefault, &qr);
    EncodeFn fn = (EncodeFn)p;
    cuuint64_t dims[2]    = { (cuuint64_t)NUMF, (cuuint64_t)rows };
    cuuint64_t strides[1] = { (cuuint64_t)NUMF * 4ull };
    cuuint32_t box[2]     = { 32u, box_rows };   // 128B x box_rows, SW128
    cuuint32_t es[2]      = { 1u, 1u };
    fn(m, CU_TENSOR_MAP_DATA_TYPE_FLOAT32, 2, (void*)ptr, dims, strides, box, es,
       CU_TENSOR_MAP_INTERLEAVE_NONE, CU_TENSOR_MAP_SWIZZLE_128B,
       CU_TENSOR_MAP_L2_PROMOTION_L2_128B, CU_TENSOR_MAP_FLOAT_OOB_FILL_NONE);
}

extern "C" void kernel_launch(void* const* d_in, const int* in_sizes, int n_in,
                              void* d_out, int out_size) {
    const float* wf  = (const float*)d_in[0];
    const float* bf  = (const float*)d_in[1];
    const float* stm = (const float*)d_in[2];
    const float* W0  = (const float*)d_in[3];
    const float* b0  = (const float*)d_in[4];
    const float* W1  = (const float*)d_in[5];
    const float* b1  = (const float*)d_in[6];
    const float* W2  = (const float*)d_in[7];
    const float* b2  = (const float*)d_in[8];
    const float* W3  = (const float*)d_in[9];
    const float* b3  = (const float*)d_in[10];
    float* out = (float*)d_out;

    CUtensorMap mW, mB, mW0;
    encode_map(&mW,  wf, 4096, 128);
    encode_map(&mB,  bf, 4096, 128);
    encode_map(&mW0, W0, 256,  256);

    cudaFuncSetAttribute(nn_gemm, cudaFuncAttributeMaxDynamicSharedMemorySize, SMEM1);
    cudaFuncSetAttribute(nn_head, cudaFuncAttributeMaxDynamicSharedMemorySize, SMEM2);

    nn_gemm<<<GRID1, 288, SMEM1>>>(mW, mB, mW0);
    nn_head<<<256, 256, SMEM2>>>(stm, b0, W1, b1, W2, b2, W3, b3, out);
}

// round 11
// speedup vs baseline: 5.6997x; 1.0388x over previous
#include <cuda_runtime.h>
#include <cuda.h>
#include <cstdint>

// ---------------- constants ----------------
#define NUMF    41024
#define KCHUNK  32                  // floats per pipeline chunk (= 2 k16 mma steps)
#define CHPM    1282                // chunks per M-tile (41024/32)
#define NMT     64                  // M-tiles (32 white + 32 black)
#define TOTC    (NMT * CHPM)        // 82048 total chunk-columns
#define GRID1   148                 // one CTA per SM
#define STAGES  4
#define ASTG    16384               // A: 128 rows x 128B
#define BSTG    32768               // B: 256 rows x 128B
#define STGB    (ASTG + BSTG)       // 49152
#define SMEM1   (2048 + STAGES * STGB)   // 198656

// per-CTA partials: [cta][part 0/1][128 rows x 256 neurons]
__device__ float g_part[GRID1][2][128 * 256];
// dense accumulator (+b0): rows 0..4095 white, 4096..8191 black
__device__ float g_acc[8192 * 256];

// ---------------- device helpers ----------------
__device__ __forceinline__ uint32_t smem_u32(const void* p) {
    uint32_t a;
    asm("{ .reg .u64 t; cvta.to.shared.u64 t, %1; cvt.u32.u64 %0, t; }" : "=r"(a) : "l"(p));
    return a;
}
__device__ __forceinline__ void mbar_init(uint32_t a, uint32_t c) {
    asm volatile("mbarrier.init.shared.b64 [%0], %1;" :: "r"(a), "r"(c) : "memory");
}
__device__ __forceinline__ void mbar_expect_tx(uint32_t a, uint32_t b) {
    asm volatile("mbarrier.arrive.expect_tx.shared.b64 _, [%0], %1;" :: "r"(a), "r"(b) : "memory");
}
__device__ __forceinline__ void mbar_arrive(uint32_t a) {
    asm volatile("mbarrier.arrive.shared.b64 _, [%0];" :: "r"(a) : "memory");
}
__device__ __forceinline__ void mbar_wait(uint32_t mbar, uint32_t parity) {
    asm volatile(
        "{\n\t.reg .pred P;\n\t"
        "LW_%=:\n\t"
        "mbarrier.try_wait.parity.acquire.cta.shared::cta.b64 P, [%0], %1, 0x989680;\n\t"
        "@P bra.uni LD_%=;\n\t"
        "bra.uni LW_%=;\n\t"
        "LD_%=:\n\t}"
        :: "r"(mbar), "r"(parity) : "memory");
}
__device__ __forceinline__ void tma2d(uint32_t dst, const CUtensorMap* m, int x, int y, uint32_t mbar) {
    asm volatile(
        "cp.async.bulk.tensor.2d.shared::cta.global.tile.mbarrier::complete_tx::bytes "
        "[%0], [%1, {%2, %3}], [%4];"
        :: "r"(dst), "l"(m), "r"(x), "r"(y), "r"(mbar) : "memory");
}
// pack two fp32 -> f16x2 {lo, hi}
__device__ __forceinline__ uint32_t f2h2(float lo, float hi) {
    uint32_t r;
    asm("cvt.rn.f16x2.f32 %0, %2, %1;" : "=r"(r) : "f"(lo), "f"(hi));
    return r;
}
__device__ __forceinline__ void mma_f16(float* c, const uint32_t* a, const uint32_t* b) {
    asm volatile(
        "mma.sync.aligned.m16n8k16.row.col.f32.f16.f16.f32 "
        "{%0,%1,%2,%3}, {%4,%5,%6,%7}, {%8,%9}, {%0,%1,%2,%3};"
        : "+f"(c[0]), "+f"(c[1]), "+f"(c[2]), "+f"(c[3])
        : "r"(a[0]), "r"(a[1]), "r"(a[2]), "r"(a[3]), "r"(b[0]), "r"(b[1]));
}

// ---------------- kernel 1: layer-0 GEMM (fp16 mma.sync, balanced 148-CTA split) ----------------
__global__ void __launch_bounds__(288, 1) nn_gemm(
    const __grid_constant__ CUtensorMap tmW,
    const __grid_constant__ CUtensorMap tmB,
    const __grid_constant__ CUtensorMap tmW0)
{
    extern __shared__ char raw[];
    char* base = (char*)(((uintptr_t)raw + 1023u) & ~(uintptr_t)1023u);
    uint32_t base_u   = smem_u32(base);
    uint32_t mb_full  = base_u;            // STAGES x 8B
    uint32_t mb_empty = base_u + 512;      // STAGES x 8B
    char* tiles       = base + 1024;
    uint32_t tiles_u  = base_u + 1024;

    const int tid  = threadIdx.x;
    const int wid  = tid >> 5;
    const int lane = tid & 31;
    const int bid  = blockIdx.x;

    const int cs = (int)((long long)bid * TOTC / GRID1);        // start chunk
    const int ce = (int)((long long)(bid + 1) * TOTC / GRID1);  // end chunk
    const int nc = ce - cs;                                     // 554 or 555
    const int mt0 = cs / CHPM;
    const int mt1 = (ce - 1) / CHPM;                            // mt0 or mt0+1

    if (tid == 0) {
        for (int s = 0; s < STAGES; s++) {
            mbar_init(mb_full  + s * 8, 1);
            mbar_init(mb_empty + s * 8, 256);
        }
        asm volatile("fence.proxy.async.shared::cta;" ::: "memory");
    }
    __syncthreads();

    if (wid == 8) {
        if (lane == 0) {
            // ---------------- producer ----------------
#define ISSUE(c_, s_) do {                                           \
            int mt_ = (c_) / CHPM;                                   \
            int kc_ = (c_) - mt_ * CHPM;                             \
            const CUtensorMap* mp_ = (mt_ < 32) ? &tmW : &tmB;       \
            uint32_t mb_ = mb_full + (s_) * 8;                       \
            mbar_expect_tx(mb_, STGB);                               \
            uint32_t t_ = tiles_u + (s_) * STGB;                     \
            tma2d(t_,        mp_,   kc_ * KCHUNK, (mt_ & 31) * 128, mb_); \
            tma2d(t_ + ASTG, &tmW0, kc_ * KCHUNK, 0,                mb_); \
        } while (0)
            ISSUE(cs, 0); ISSUE(cs + 1, 1); ISSUE(cs + 2, 2); ISSUE(cs + 3, 3);
            int s = 0, ep = 0;
            for (int j = STAGES; j < nc; j++) {
                mbar_wait(mb_empty + s * 8, ep);
                ISSUE(cs + j, s);
                if (++s == STAGES) { s = 0; ep ^= 1; }
            }
#undef ISSUE
        }
    } else {
        // ---------------- consumers ----------------
        const int wm = (wid >> 2) * 64;      // warp M offset (0/64)
        const int wn = (wid & 3) * 64;       // warp N offset (0/64/128/192)
        const int g  = lane >> 2;            // 0..7
        const int t  = lane & 3;             // 0..3

        // conflict-free swizzled byte offsets (validated in R7)
        int off[2][2];
        #pragma unroll
        for (int s_ = 0; s_ < 2; s_++)
            #pragma unroll
            for (int h_ = 0; h_ < 2; h_++)
                off[s_][h_] = ((32 * s_ + 16 * h_ + 8 * (t & 1) + 64 * (t >> 1)) ^ (g << 4));

        float c[4][8][4];
        #pragma unroll
        for (int mi = 0; mi < 4; mi++)
            #pragma unroll
            for (int ni = 0; ni < 8; ni++)
                #pragma unroll
                for (int r = 0; r < 4; r++) c[mi][ni][r] = 0.f;

        // local index of the last chunk of part 0 (or -1 if single part)
        const int jb = (mt1 > mt0) ? ((mt0 + 1) * CHPM - 1 - cs) : -1;

        int s = 0, fp = 0;
        for (int j = 0; j < nc; j++) {
            mbar_wait(mb_full + s * 8, fp);
            const char* Ast = tiles + s * STGB;
            const char* Bst = Ast + ASTG;

            #pragma unroll
            for (int st = 0; st < 2; st++) {
                uint32_t a[4][4];
                #pragma unroll
                for (int mi = 0; mi < 4; mi++) {
                    const char* pr = Ast + (wm + mi * 16 + g) * 128;
                    float2 v00 = *(const float2*)(pr + off[st][0]);
                    float2 v10 = *(const float2*)(pr + 1024 + off[st][0]);
                    float2 v01 = *(const float2*)(pr + off[st][1]);
                    float2 v11 = *(const float2*)(pr + 1024 + off[st][1]);
                    a[mi][0] = f2h2(v00.x, v00.y);
                    a[mi][1] = f2h2(v10.x, v10.y);
                    a[mi][2] = f2h2(v01.x, v01.y);
                    a[mi][3] = f2h2(v11.x, v11.y);
                }
                uint32_t b[8][2];
                #pragma unroll
                for (int ni = 0; ni < 8; ni++) {
                    const char* pr = Bst + (wn + ni * 8 + g) * 128;
                    float2 u0 = *(const float2*)(pr + off[st][0]);
                    float2 u1 = *(const float2*)(pr + off[st][1]);
                    b[ni][0] = f2h2(u0.x, u0.y);
                    b[ni][1] = f2h2(u1.x, u1.y);
                }
                #pragma unroll
                for (int mi = 0; mi < 4; mi++)
                    #pragma unroll
                    for (int ni = 0; ni < 8; ni++)
                        mma_f16(c[mi][ni], a[mi], b[ni]);
            }
            mbar_arrive(mb_empty + s * 8);
            if (++s == STAGES) { s = 0; fp ^= 1; }

            if (j == jb) {
                // flush part 0, reset accumulators
                float* dst = g_part[bid][0];
                #pragma unroll
                for (int ni = 0; ni < 8; ni++) {
                    const int col = wn + ni * 8 + (t << 1);
                    #pragma unroll
                    for (int mi = 0; mi < 4; mi++) {
                        const int r = wm + mi * 16 + g;
                        *(float2*)(dst + (size_t)r * 256 + col)       = make_float2(c[mi][ni][0], c[mi][ni][1]);
                        *(float2*)(dst + (size_t)(r + 8) * 256 + col) = make_float2(c[mi][ni][2], c[mi][ni][3]);
                        c[mi][ni][0] = c[mi][ni][1] = c[mi][ni][2] = c[mi][ni][3] = 0.f;
                    }
                }
            }
        }

        // final flush (part 1 if two parts, else part 0)
        {
            float* dst = g_part[bid][(mt1 > mt0) ? 1 : 0];
            #pragma unroll
            for (int ni = 0; ni < 8; ni++) {
                const int col = wn + ni * 8 + (t << 1);
                #pragma unroll
                for (int mi = 0; mi < 4; mi++) {
                    const int r = wm + mi * 16 + g;
                    *(float2*)(dst + (size_t)r * 256 + col)       = make_float2(c[mi][ni][0], c[mi][ni][1]);
                    *(float2*)(dst + (size_t)(r + 8) * 256 + col) = make_float2(c[mi][ni][2], c[mi][ni][3]);
                }
            }
        }
    }
}

// ---------------- kernel 1.5: reduce partials -> dense g_acc (+b0) ----------------
// CTA containing chunk c: largest i with floor(i*TOTC/GRID1) <= c.
__device__ __forceinline__ int cover_cta(int c) {
    return (int)(((long long)(c + 1) * GRID1 - 1) / TOTC);
}
__device__ __forceinline__ int gather_parts(int mt, const float** ptr) {
    int c0 = mt * CHPM;
    int iA = cover_cta(c0);
    int iB = cover_cta(c0 + CHPM - 1);
    int n = 0;
    for (int i = iA; i <= iB && n < 4; i++) {
        int si = (int)((long long)i * TOTC / GRID1);
        int slot = (si / CHPM == mt) ? 0 : 1;
        ptr[n++] = g_part[i][slot];
    }
    return n;
}

__global__ void __launch_bounds__(256) nn_reduce(const float* __restrict__ b0) {
    const int mt   = blockIdx.x >> 1;       // M-tile 0..63
    const int half = blockIdx.x & 1;        // rows [half*64, half*64+64)
    const float* ps[4];
    const int n = gather_parts(mt, ps);

    const int base = half * 64 * 256;       // float offset within tile
    float* dst = g_acc + (size_t)mt * 128 * 256 + base;
    const float4* b0v = (const float4*)b0;

    // 64 rows x 256 cols = 4096 float4; 256 threads x 16 iters
    for (int i = threadIdx.x; i < 4096; i += 256) {
        float4 s = b0v[i & 63];             // col4 index = i % 64
        #pragma unroll 4
        for (int k = 0; k < 4; k++) {
            if (k < n) {
                float4 v = ((const float4*)(ps[k] + base))[i];
                s.x += v.x; s.y += v.y; s.z += v.z; s.w += v.w;
            }
        }
        ((float4*)dst)[i] = s;
    }
}

// ---------------- kernel 2: blend + clip + small MLP head ----------------
#define SW1_PITCH 513
#define SW2_PITCH 33
#define SMEM2 ((32*SW1_PITCH + 32*SW2_PITCH + 8*512 + 8*32) * 4)

__global__ void __launch_bounds__(256) nn_head(
    const float* __restrict__ stm,
    const float* __restrict__ W1, const float* __restrict__ b1,
    const float* __restrict__ W2, const float* __restrict__ b2,
    const float* __restrict__ W3, const float* __restrict__ b3,
    float* __restrict__ out)
{
    extern __shared__ float sm[];
    float* sW1 = sm;                               // 32 x 513
    float* sW2 = sW1 + 32 * SW1_PITCH;             // 32 x 33
    float* sl1 = sW2 + 32 * SW2_PITCH;             // 8 warps x 512
    float* sl2 = sl1 + 8 * 512;                    // 8 warps x 32

    int tid = threadIdx.x;
    for (int i = tid; i < 32 * 512; i += 256) sW1[(i >> 9) * SW1_PITCH + (i & 511)] = W1[i];
    for (int i = tid; i < 32 * 32;  i += 256) sW2[(i >> 5) * SW2_PITCH + (i & 31)]  = W2[i];
    __syncthreads();

    int w = tid >> 5, j = tid & 31;
    float* l1 = sl1 + w * 512;
    float* l2 = sl2 + w * 32;
    float bj1 = b1[j], bj2 = b2[j], w3j = W3[j], b3v = b3[0];

    for (int q = 0; q < 2; q++) {
        int b = blockIdx.x * 16 + w * 2 + q;
        const float* aw = g_acc + (size_t)b * 256;
        const float* ab = g_acc + (size_t)(4096 + b) * 256;
        float s = stm[b];
        for (int tt = j; tt < 256; tt += 32) {
            float wv = aw[tt], bv = ab[tt];
            float x0 = s * wv + (1.f - s) * bv;
            float x1 = s * bv + (1.f - s) * wv;
            l1[tt]       = fminf(fmaxf(x0, 0.f), 1.f);
            l1[256 + tt] = fminf(fmaxf(x1, 0.f), 1.f);
        }
        __syncwarp();
        float a2 = bj1;
        const float* wr = sW1 + j * SW1_PITCH;
        #pragma unroll 8
        for (int k = 0; k < 512; k++) a2 += wr[k] * l1[k];
        a2 = fminf(fmaxf(a2, 0.f), 1.f);
        l2[j] = a2;
        __syncwarp();
        float a3 = bj2;
        const float* wr2 = sW2 + j * SW2_PITCH;
        #pragma unroll
        for (int k = 0; k < 32; k++) a3 += wr2[k] * l2[k];
        a3 = fminf(fmaxf(a3, 0.f), 1.f);
        float v = w3j * a3;
        #pragma unroll
        for (int o = 16; o > 0; o >>= 1) v += __shfl_xor_sync(0xffffffffu, v, o);
        if (j == 0) out[b] = v + b3v;
        __syncwarp();
    }
}

// ---------------- host ----------------
typedef CUresult (*EncodeFn)(CUtensorMap*, CUtensorMapDataType, cuuint32_t, void*,
                             const cuuint64_t*, const cuuint64_t*, const cuuint32_t*, const cuuint32_t*,
                             CUtensorMapInterleave, CUtensorMapSwizzle,
                             CUtensorMapL2promotion, CUtensorMapFloatOOBfill);

static void encode_map(CUtensorMap* m, const void* ptr, unsigned long long rows, unsigned box_rows) {
    void* p = nullptr;
    cudaDriverEntryPointQueryResult qr;
    cudaGetDriverEntryPointByVersion("cuTensorMapEncodeTiled", &p, 12000, cudaEnableDefault, &qr);
    EncodeFn fn = (EncodeFn)p;
    cuuint64_t dims[2]    = { (cuuint64_t)NUMF, (cuuint64_t)rows };
    cuuint64_t strides[1] = { (cuuint64_t)NUMF * 4ull };
    cuuint32_t box[2]     = { 32u, box_rows };   // 128B x box_rows, SW128
    cuuint32_t es[2]      = { 1u, 1u };
    fn(m, CU_TENSOR_MAP_DATA_TYPE_FLOAT32, 2, (void*)ptr, dims, strides, box, es,
       CU_TENSOR_MAP_INTERLEAVE_NONE, CU_TENSOR_MAP_SWIZZLE_128B,
       CU_TENSOR_MAP_L2_PROMOTION_L2_128B, CU_TENSOR_MAP_FLOAT_OOB_FILL_NONE);
}

extern "C" void kernel_launch(void* const* d_in, const int* in_sizes, int n_in,
                              void* d_out, int out_size) {
    const float* wf  = (const float*)d_in[0];
    const float* bf  = (const float*)d_in[1];
    const float* stm = (const float*)d_in[2];
    const float* W0  = (const float*)d_in[3];
    const float* b0  = (const float*)d_in[4];
    const float* W1  = (const float*)d_in[5];
    const float* b1  = (const float*)d_in[6];
    const float* W2  = (const float*)d_in[7];
    const float* b2  = (const float*)d_in[8];
    const float* W3  = (const float*)d_in[9];
    const float* b3  = (const float*)d_in[10];
    float* out = (float*)d_out;

    CUtensorMap mW, mB, mW0;
    encode_map(&mW,  wf, 4096, 128);
    encode_map(&mB,  bf, 4096, 128);
    encode_map(&mW0, W0, 256,  256);

    cudaFuncSetAttribute(nn_gemm, cudaFuncAttributeMaxDynamicSharedMemorySize, SMEM1);
    cudaFuncSetAttribute(nn_head, cudaFuncAttributeMaxDynamicSharedMemorySize, SMEM2);

    nn_gemm<<<GRID1, 288, SMEM1>>>(mW, mB, mW0);
    nn_reduce<<<128, 256>>>(b0);
    nn_head<<<256, 256, SMEM2>>>(stm, W1, b1, W2, b2, W3, b3, out);
}

// round 12
// speedup vs baseline: 5.9058x; 1.0362x over previous
#include <cuda_runtime.h>
#include <cuda.h>
#include <cuda_fp16.h>
#include <cstdint>

// ---------------- constants ----------------
#define NUMF    41024
#define KCHUNK  64                  // k-values per pipeline chunk (= 4 k16 mma steps)
#define CHPM    641                 // chunks per M-tile (41024/64)
#define NMT     64                  // M-tiles (32 white + 32 black)
#define TOTC    (NMT * CHPM)        // 41024 total chunk-columns
#define GRID1   148                 // one CTA per SM
#define STAGES  3
#define ASTG    32768               // A: 2 sub-tiles x (128 rows x 128B) fp32
#define BSTG    32768               // B: 256 rows x 128B fp16 (64 k)
#define STGB    (ASTG + BSTG)       // 65536
#define SMEM1   (2048 + STAGES * STGB)   // 198656

// per-CTA partials: [cta][part 0/1][128 rows x 256 neurons]
__device__ float g_part[GRID1][2][128 * 256];
// dense accumulator (+b0): rows 0..4095 white, 4096..8191 black
__device__ float g_acc[8192 * 256];
// W0 pre-converted to fp16, fragment-packed per 64-half group
__device__ __align__(1024) __half g_w0h[256 * NUMF];

// ---------------- device helpers ----------------
__device__ __forceinline__ uint32_t smem_u32(const void* p) {
    uint32_t a;
    asm("{ .reg .u64 t; cvta.to.shared.u64 t, %1; cvt.u32.u64 %0, t; }" : "=r"(a) : "l"(p));
    return a;
}
__device__ __forceinline__ void mbar_init(uint32_t a, uint32_t c) {
    asm volatile("mbarrier.init.shared.b64 [%0], %1;" :: "r"(a), "r"(c) : "memory");
}
__device__ __forceinline__ void mbar_expect_tx(uint32_t a, uint32_t b) {
    asm volatile("mbarrier.arrive.expect_tx.shared.b64 _, [%0], %1;" :: "r"(a), "r"(b) : "memory");
}
__device__ __forceinline__ void mbar_arrive(uint32_t a) {
    asm volatile("mbarrier.arrive.shared.b64 _, [%0];" :: "r"(a) : "memory");
}
__device__ __forceinline__ void mbar_wait(uint32_t mbar, uint32_t parity) {
    asm volatile(
        "{\n\t.reg .pred P;\n\t"
        "LW_%=:\n\t"
        "mbarrier.try_wait.parity.acquire.cta.shared::cta.b64 P, [%0], %1, 0x989680;\n\t"
        "@P bra.uni LD_%=;\n\t"
        "bra.uni LW_%=;\n\t"
        "LD_%=:\n\t}"
        :: "r"(mbar), "r"(parity) : "memory");
}
__device__ __forceinline__ void tma2d(uint32_t dst, const CUtensorMap* m, int x, int y, uint32_t mbar) {
    asm volatile(
        "cp.async.bulk.tensor.2d.shared::cta.global.tile.mbarrier::complete_tx::bytes "
        "[%0], [%1, {%2, %3}], [%4];"
        :: "r"(dst), "l"(m), "r"(x), "r"(y), "r"(mbar) : "memory");
}
// pack two fp32 -> f16x2 {lo, hi}
__device__ __forceinline__ uint32_t f2h2(float lo, float hi) {
    uint32_t r;
    asm("cvt.rn.f16x2.f32 %0, %2, %1;" : "=r"(r) : "f"(lo), "f"(hi));
    return r;
}
__device__ __forceinline__ void mma_f16(float* c, const uint32_t* a, const uint32_t* b) {
    asm volatile(
        "mma.sync.aligned.m16n8k16.row.col.f32.f16.f16.f32 "
        "{%0,%1,%2,%3}, {%4,%5,%6,%7}, {%8,%9}, {%0,%1,%2,%3};"
        : "+f"(c[0]), "+f"(c[1]), "+f"(c[2]), "+f"(c[3])
        : "r"(a[0]), "r"(a[1]), "r"(a[2]), "r"(a[3]), "r"(b[0]), "r"(b[1]));
}

// ---------------- kernel 0: convert W0 -> fragment-packed fp16 ----------------
// Within each 64-half group of a row, dest half d (r = d&63):
//   slot = r>>2 (bit0 = t&1, bit1 = st, bit2 = c, bit3 = t>>1), idx = r&3 (h = idx>>1, e = idx&1)
//   source k offset = c*32 + 16*(t>>1) + 2*(t&1) + 8*st + 4*h + e
__global__ void __launch_bounds__(256) nn_cvt(const float* __restrict__ W0) {
    const int n = blockIdx.x;                 // 0..255
    const float* src = W0 + (size_t)n * NUMF;
    __half* dst = g_w0h + (size_t)n * NUMF;
    for (int d = threadIdx.x; d < NUMF; d += 256) {
        int r = d & 63, base = d & ~63;
        int slot = r >> 2, idx = r & 3;
        int t  = (slot & 1) | ((slot >> 3) << 1);
        int st = (slot >> 1) & 1;
        int c  = (slot >> 2) & 1;
        int k  = base + c * 32 + 16 * (t >> 1) + 2 * (t & 1) + 8 * st + 4 * (idx >> 1) + (idx & 1);
        dst[d] = __float2half(src[k]);
    }
}

// ---------------- kernel 1: layer-0 GEMM (fp16 mma.sync, fp16 B, 148-CTA split) ----------------
__global__ void __launch_bounds__(288, 1) nn_gemm(
    const __grid_constant__ CUtensorMap tmW,
    const __grid_constant__ CUtensorMap tmB,
    const __grid_constant__ CUtensorMap tmW0h)
{
    extern __shared__ char raw[];
    char* base = (char*)(((uintptr_t)raw + 1023u) & ~(uintptr_t)1023u);
    uint32_t base_u   = smem_u32(base);
    uint32_t mb_full  = base_u;            // STAGES x 8B
    uint32_t mb_empty = base_u + 512;      // STAGES x 8B
    char* tiles       = base + 1024;
    uint32_t tiles_u  = base_u + 1024;

    const int tid  = threadIdx.x;
    const int wid  = tid >> 5;
    const int lane = tid & 31;
    const int bid  = blockIdx.x;

    const int cs = (int)((long long)bid * TOTC / GRID1);        // start chunk
    const int ce = (int)((long long)(bid + 1) * TOTC / GRID1);  // end chunk
    const int nc = ce - cs;                                     // 277 or 278
    const int mt0 = cs / CHPM;
    const int mt1 = (ce - 1) / CHPM;                            // mt0 or mt0+1

    if (tid == 0) {
        for (int s = 0; s < STAGES; s++) {
            mbar_init(mb_full  + s * 8, 1);
            mbar_init(mb_empty + s * 8, 256);
        }
        asm volatile("fence.proxy.async.shared::cta;" ::: "memory");
    }
    __syncthreads();

    if (wid == 8) {
        if (lane == 0) {
            // ---------------- producer ----------------
#define ISSUE(c_, s_) do {                                           \
            int mt_ = (c_) / CHPM;                                   \
            int kc_ = (c_) - mt_ * CHPM;                             \
            const CUtensorMap* mp_ = (mt_ < 32) ? &tmW : &tmB;       \
            uint32_t mb_ = mb_full + (s_) * 8;                       \
            mbar_expect_tx(mb_, STGB);                               \
            uint32_t t_ = tiles_u + (s_) * STGB;                     \
            tma2d(t_,         mp_,   kc_ * 64,      (mt_ & 31) * 128, mb_); \
            tma2d(t_ + 16384, mp_,   kc_ * 64 + 32, (mt_ & 31) * 128, mb_); \
            tma2d(t_ + ASTG, &tmW0h, kc_ * 64,      0,                mb_); \
        } while (0)
            ISSUE(cs, 0); ISSUE(cs + 1, 1); ISSUE(cs + 2, 2);
            int s = 0, ep = 0;
            for (int j = STAGES; j < nc; j++) {
                mbar_wait(mb_empty + s * 8, ep);
                ISSUE(cs + j, s);
                if (++s == STAGES) { s = 0; ep ^= 1; }
            }
#undef ISSUE
        }
    } else {
        // ---------------- consumers ----------------
        const int wm = (wid >> 2) * 64;      // warp M offset (0/64)
        const int wn = (wid & 3) * 64;       // warp N offset (0/64/128/192)
        const int g  = lane >> 2;            // 0..7
        const int t  = lane & 3;             // 0..3

        // A: conflict-free swizzled byte offsets (validated R7); st = kstep&1
        int aoff[2][2];
        #pragma unroll
        for (int s_ = 0; s_ < 2; s_++)
            #pragma unroll
            for (int h_ = 0; h_ < 2; h_++)
                aoff[s_][h_] = ((32 * s_ + 16 * h_ + 8 * (t & 1) + 64 * (t >> 1)) ^ (g << 4));
        // B: one LDS.64 per (ni, kstep); slot = P(t) + 2*st + 4*c
        const int Pt = (t & 1) + 8 * (t >> 1);
        int boff[4];
        #pragma unroll
        for (int ks = 0; ks < 4; ks++)
            boff[ks] = (((Pt + 2 * (ks & 1) + 4 * (ks >> 1)) * 8) ^ (g << 4));

        float c[4][8][4];
        #pragma unroll
        for (int mi = 0; mi < 4; mi++)
            #pragma unroll
            for (int ni = 0; ni < 8; ni++)
                #pragma unroll
                for (int r = 0; r < 4; r++) c[mi][ni][r] = 0.f;

        // local index of the last chunk of part 0 (or -1 if single part)
        const int jb = (mt1 > mt0) ? ((mt0 + 1) * CHPM - 1 - cs) : -1;

        int s = 0, fp = 0;
        for (int j = 0; j < nc; j++) {
            mbar_wait(mb_full + s * 8, fp);
            const char* Ast = tiles + s * STGB;
            const char* Bst = Ast + ASTG;

            #pragma unroll
            for (int ks = 0; ks < 4; ks++) {
                const char* Asub = Ast + (ks >> 1) * 16384;
                const int st = ks & 1;
                uint32_t a[4][4];
                #pragma unroll
                for (int mi = 0; mi < 4; mi++) {
                    const char* pr = Asub + (wm + mi * 16 + g) * 128;
                    float2 v00 = *(const float2*)(pr + aoff[st][0]);
                    float2 v10 = *(const float2*)(pr + 1024 + aoff[st][0]);
                    float2 v01 = *(const float2*)(pr + aoff[st][1]);
                    float2 v11 = *(const float2*)(pr + 1024 + aoff[st][1]);
                    a[mi][0] = f2h2(v00.x, v00.y);
                    a[mi][1] = f2h2(v10.x, v10.y);
                    a[mi][2] = f2h2(v01.x, v01.y);
                    a[mi][3] = f2h2(v11.x, v11.y);
                }
                uint32_t b[8][2];
                #pragma unroll
                for (int ni = 0; ni < 8; ni++) {
                    uint2 v = *(const uint2*)(Bst + (wn + ni * 8 + g) * 128 + boff[ks]);
                    b[ni][0] = v.x; b[ni][1] = v.y;
                }
                #pragma unroll
                for (int mi = 0; mi < 4; mi++)
                    #pragma unroll
                    for (int ni = 0; ni < 8; ni++)
                        mma_f16(c[mi][ni], a[mi], b[ni]);
            }
            mbar_arrive(mb_empty + s * 8);
            if (++s == STAGES) { s = 0; fp ^= 1; }

            if (j == jb) {
                // flush part 0, reset accumulators
                float* dst = g_part[bid][0];
                #pragma unroll
                for (int ni = 0; ni < 8; ni++) {
                    const int col = wn + ni * 8 + (t << 1);
                    #pragma unroll
                    for (int mi = 0; mi < 4; mi++) {
                        const int r = wm + mi * 16 + g;
                        *(float2*)(dst + (size_t)r * 256 + col)       = make_float2(c[mi][ni][0], c[mi][ni][1]);
                        *(float2*)(dst + (size_t)(r + 8) * 256 + col) = make_float2(c[mi][ni][2], c[mi][ni][3]);
                        c[mi][ni][0] = c[mi][ni][1] = c[mi][ni][2] = c[mi][ni][3] = 0.f;
                    }
                }
            }
        }

        // final flush (part 1 if two parts, else part 0)
        {
            float* dst = g_part[bid][(mt1 > mt0) ? 1 : 0];
            #pragma unroll
            for (int ni = 0; ni < 8; ni++) {
                const int col = wn + ni * 8 + (t << 1);
                #pragma unroll
                for (int mi = 0; mi < 4; mi++) {
                    const int r = wm + mi * 16 + g;
                    *(float2*)(dst + (size_t)r * 256 + col)       = make_float2(c[mi][ni][0], c[mi][ni][1]);
                    *(float2*)(dst + (size_t)(r + 8) * 256 + col) = make_float2(c[mi][ni][2], c[mi][ni][3]);
                }
            }
        }
    }
}

// ---------------- kernel 1.5: reduce partials -> dense g_acc (+b0) ----------------
__device__ __forceinline__ int cover_cta(int c) {
    return (int)(((long long)(c + 1) * GRID1 - 1) / TOTC);
}
__device__ __forceinline__ int gather_parts(int mt, const float** ptr) {
    int c0 = mt * CHPM;
    int iA = cover_cta(c0);
    int iB = cover_cta(c0 + CHPM - 1);
    int n = 0;
    for (int i = iA; i <= iB && n < 4; i++) {
        int si = (int)((long long)i * TOTC / GRID1);
        int slot = (si / CHPM == mt) ? 0 : 1;
        ptr[n++] = g_part[i][slot];
    }
    return n;
}

__global__ void __launch_bounds__(256) nn_reduce(const float* __restrict__ b0) {
    const int mt   = blockIdx.x >> 1;
    const int half = blockIdx.x & 1;
    const float* ps[4];
    const int n = gather_parts(mt, ps);

    const int base = half * 64 * 256;
    float* dst = g_acc + (size_t)mt * 128 * 256 + base;
    const float4* b0v = (const float4*)b0;

    for (int i = threadIdx.x; i < 4096; i += 256) {
        float4 s = b0v[i & 63];
        #pragma unroll 4
        for (int k = 0; k < 4; k++) {
            if (k < n) {
                float4 v = ((const float4*)(ps[k] + base))[i];
                s.x += v.x; s.y += v.y; s.z += v.z; s.w += v.w;
            }
        }
        ((float4*)dst)[i] = s;
    }
}

// ---------------- kernel 2: blend + clip + small MLP head ----------------
#define SW1_PITCH 513
#define SW2_PITCH 33
#define SMEM2 ((32*SW1_PITCH + 32*SW2_PITCH + 8*512 + 8*32) * 4)

__global__ void __launch_bounds__(256) nn_head(
    const float* __restrict__ stm,
    const float* __restrict__ W1, const float* __restrict__ b1,
    const float* __restrict__ W2, const float* __restrict__ b2,
    const float* __restrict__ W3, const float* __restrict__ b3,
    float* __restrict__ out)
{
    extern __shared__ float sm[];
    float* sW1 = sm;                               // 32 x 513
    float* sW2 = sW1 + 32 * SW1_PITCH;             // 32 x 33
    float* sl1 = sW2 + 32 * SW2_PITCH;             // 8 warps x 512
    float* sl2 = sl1 + 8 * 512;                    // 8 warps x 32

    int tid = threadIdx.x;
    for (int i = tid; i < 32 * 512; i += 256) sW1[(i >> 9) * SW1_PITCH + (i & 511)] = W1[i];
    for (int i = tid; i < 32 * 32;  i += 256) sW2[(i >> 5) * SW2_PITCH + (i & 31)]  = W2[i];
    __syncthreads();

    int w = tid >> 5, j = tid & 31;
    float* l1 = sl1 + w * 512;
    float* l2 = sl2 + w * 32;
    float bj1 = b1[j], bj2 = b2[j], w3j = W3[j], b3v = b3[0];

    for (int q = 0; q < 2; q++) {
        int b = blockIdx.x * 16 + w * 2 + q;
        const float* aw = g_acc + (size_t)b * 256;
        const float* ab = g_acc + (size_t)(4096 + b) * 256;
        float s = stm[b];
        for (int tt = j; tt < 256; tt += 32) {
            float wv = aw[tt], bv = ab[tt];
            float x0 = s * wv + (1.f - s) * bv;
            float x1 = s * bv + (1.f - s) * wv;
            l1[tt]       = fminf(fmaxf(x0, 0.f), 1.f);
            l1[256 + tt] = fminf(fmaxf(x1, 0.f), 1.f);
        }
        __syncwarp();
        float a2 = bj1;
        const float* wr = sW1 + j * SW1_PITCH;
        #pragma unroll 8
        for (int k = 0; k < 512; k++) a2 += wr[k] * l1[k];
        a2 = fminf(fmaxf(a2, 0.f), 1.f);
        l2[j] = a2;
        __syncwarp();
        float a3 = bj2;
        const float* wr2 = sW2 + j * SW2_PITCH;
        #pragma unroll
        for (int k = 0; k < 32; k++) a3 += wr2[k] * l2[k];
        a3 = fminf(fmaxf(a3, 0.f), 1.f);
        float v = w3j * a3;
        #pragma unroll
        for (int o = 16; o > 0; o >>= 1) v += __shfl_xor_sync(0xffffffffu, v, o);
        if (j == 0) out[b] = v + b3v;
        __syncwarp();
    }
}

// ---------------- host ----------------
typedef CUresult (*EncodeFn)(CUtensorMap*, CUtensorMapDataType, cuuint32_t, void*,
                             const cuuint64_t*, const cuuint64_t*, const cuuint32_t*, const cuuint32_t*,
                             CUtensorMapInterleave, CUtensorMapSwizzle,
                             CUtensorMapL2promotion, CUtensorMapFloatOOBfill);

static EncodeFn get_encoder() {
    void* p = nullptr;
    cudaDriverEntryPointQueryResult qr;
    cudaGetDriverEntryPointByVersion("cuTensorMapEncodeTiled", &p, 12000, cudaEnableDefault, &qr);
    return (EncodeFn)p;
}

static void encode_f32(CUtensorMap* m, const void* ptr, unsigned long long rows) {
    cuuint64_t dims[2]    = { (cuuint64_t)NUMF, (cuuint64_t)rows };
    cuuint64_t strides[1] = { (cuuint64_t)NUMF * 4ull };
    cuuint32_t box[2]     = { 32u, 128u };      // 128B x 128 rows, SW128
    cuuint32_t es[2]      = { 1u, 1u };
    get_encoder()(m, CU_TENSOR_MAP_DATA_TYPE_FLOAT32, 2, (void*)ptr, dims, strides, box, es,
       CU_TENSOR_MAP_INTERLEAVE_NONE, CU_TENSOR_MAP_SWIZZLE_128B,
       CU_TENSOR_MAP_L2_PROMOTION_L2_128B, CU_TENSOR_MAP_FLOAT_OOB_FILL_NONE);
}

static void encode_f16(CUtensorMap* m, const void* ptr, unsigned long long rows) {
    cuuint64_t dims[2]    = { (cuuint64_t)NUMF, (cuuint64_t)rows };
    cuuint64_t strides[1] = { (cuuint64_t)NUMF * 2ull };
    cuuint32_t box[2]     = { 64u, 256u };      // 128B x 256 rows, SW128
    cuuint32_t es[2]      = { 1u, 1u };
    get_encoder()(m, CU_TENSOR_MAP_DATA_TYPE_FLOAT16, 2, (void*)ptr, dims, strides, box, es,
       CU_TENSOR_MAP_INTERLEAVE_NONE, CU_TENSOR_MAP_SWIZZLE_128B,
       CU_TENSOR_MAP_L2_PROMOTION_L2_128B, CU_TENSOR_MAP_FLOAT_OOB_FILL_NONE);
}

extern "C" void kernel_launch(void* const* d_in, const int* in_sizes, int n_in,
                              void* d_out, int out_size) {
    const float* wf  = (const float*)d_in[0];
    const float* bf  = (const float*)d_in[1];
    const float* stm = (const float*)d_in[2];
    const float* W0  = (const float*)d_in[3];
    const float* b0  = (const float*)d_in[4];
    const float* W1  = (const float*)d_in[5];
    const float* b1  = (const float*)d_in[6];
    const float* W2  = (const float*)d_in[7];
    const float* b2  = (const float*)d_in[8];
    const float* W3  = (const float*)d_in[9];
    const float* b3  = (const float*)d_in[10];
    float* out = (float*)d_out;

    void* w0h_ptr = nullptr;
    cudaGetSymbolAddress(&w0h_ptr, g_w0h);

    CUtensorMap mW, mB, mW0h;
    encode_f32(&mW,  wf, 4096);
    encode_f32(&mB,  bf, 4096);
    encode_f16(&mW0h, w0h_ptr, 256);

    cudaFuncSetAttribute(nn_gemm, cudaFuncAttributeMaxDynamicSharedMemorySize, SMEM1);
    cudaFuncSetAttribute(nn_head, cudaFuncAttributeMaxDynamicSharedMemorySize, SMEM2);

    nn_cvt<<<256, 256>>>(W0);
    nn_gemm<<<GRID1, 288, SMEM1>>>(mW, mB, mW0h);
    nn_reduce<<<128, 256>>>(b0);
    nn_head<<<256, 256, SMEM2>>>(stm, W1, b1, W2, b2, W3, b3, out);
}

// round 13
// speedup vs baseline: 6.0280x; 1.0207x over previous
#include <cuda_runtime.h>
#include <cuda.h>
#include <cuda_fp16.h>
#include <cstdint>

// ---------------- constants ----------------
#define NUMF    41024
#define KCHUNK  64                  // k-values per pipeline chunk (= 4 k16 mma steps)
#define CHPM    641                 // chunks per M-tile (41024/64)
#define NMT     64                  // M-tiles (32 white + 32 black)
#define TOTC    (NMT * CHPM)        // 41024 total chunk-columns
#define GRID1   148                 // one CTA per SM
#define STAGES  3
#define ASTG    32768               // A: 2 sub-tiles x (128 rows x 128B) fp32
#define BSTG    32768               // B: 256 rows x 128B fp16 (64 k)
#define STGB    (ASTG + BSTG)       // 65536
#define SMEM1   (2048 + STAGES * STGB)   // 198656

// per-CTA partials: [cta][part 0/1][128 rows x 256 neurons]
__device__ float g_part[GRID1][2][128 * 256];
// dense accumulator (+b0): rows 0..4095 white, 4096..8191 black
__device__ float g_acc[8192 * 256];
// W0 pre-converted to fp16, fragment-packed per 64-half group
__device__ __align__(1024) __half g_w0h[256 * NUMF];

// ---------------- device helpers ----------------
__device__ __forceinline__ uint32_t smem_u32(const void* p) {
    uint32_t a;
    asm("{ .reg .u64 t; cvta.to.shared.u64 t, %1; cvt.u32.u64 %0, t; }" : "=r"(a) : "l"(p));
    return a;
}
__device__ __forceinline__ void mbar_init(uint32_t a, uint32_t c) {
    asm volatile("mbarrier.init.shared.b64 [%0], %1;" :: "r"(a), "r"(c) : "memory");
}
__device__ __forceinline__ void mbar_expect_tx(uint32_t a, uint32_t b) {
    asm volatile("mbarrier.arrive.expect_tx.shared.b64 _, [%0], %1;" :: "r"(a), "r"(b) : "memory");
}
__device__ __forceinline__ void mbar_arrive(uint32_t a) {
    asm volatile("mbarrier.arrive.shared.b64 _, [%0];" :: "r"(a) : "memory");
}
__device__ __forceinline__ void mbar_wait(uint32_t mbar, uint32_t parity) {
    asm volatile(
        "{\n\t.reg .pred P;\n\t"
        "LW_%=:\n\t"
        "mbarrier.try_wait.parity.acquire.cta.shared::cta.b64 P, [%0], %1, 0x989680;\n\t"
        "@P bra.uni LD_%=;\n\t"
        "bra.uni LW_%=;\n\t"
        "LD_%=:\n\t}"
        :: "r"(mbar), "r"(parity) : "memory");
}
__device__ __forceinline__ void tma2d(uint32_t dst, const CUtensorMap* m, int x, int y, uint32_t mbar) {
    asm volatile(
        "cp.async.bulk.tensor.2d.shared::cta.global.tile.mbarrier::complete_tx::bytes "
        "[%0], [%1, {%2, %3}], [%4];"
        :: "r"(dst), "l"(m), "r"(x), "r"(y), "r"(mbar) : "memory");
}
// pack two fp32 -> f16x2 {lo, hi}
__device__ __forceinline__ uint32_t f2h2(float lo, float hi) {
    uint32_t r;
    asm("cvt.rn.f16x2.f32 %0, %2, %1;" : "=r"(r) : "f"(lo), "f"(hi));
    return r;
}
__device__ __forceinline__ void mma_f16(float* c, const uint32_t* a, const uint32_t* b) {
    asm volatile(
        "mma.sync.aligned.m16n8k16.row.col.f32.f16.f16.f32 "
        "{%0,%1,%2,%3}, {%4,%5,%6,%7}, {%8,%9}, {%0,%1,%2,%3};"
        : "+f"(c[0]), "+f"(c[1]), "+f"(c[2]), "+f"(c[3])
        : "r"(a[0]), "r"(a[1]), "r"(a[2]), "r"(a[3]), "r"(b[0]), "r"(b[1]));
}

// ---------------- kernel 0: convert W0 -> fragment-packed fp16 (vectorized) ----------------
// Dest half d (r = d&63): slot = r>>2, idx = r&3;
//   t = (slot&1)|((slot>>3)<<1), st = (slot>>1)&1, c = (slot>>2)&1
//   k(d) = base + c*32 + 16*(t>>1) + 2*(t&1) + 8*st + 4*(idx>>1) + (idx&1)
// For d % 4 == 0 the 4 dest halfs map to k offsets K0 + {0,1,4,5}.
__global__ void __launch_bounds__(512) nn_cvt(const float* __restrict__ W0) {
    const int n = blockIdx.x;                 // 0..255
    const float* src = W0 + (size_t)n * NUMF;
    __half* dst = g_w0h + (size_t)n * NUMF;
    for (int d4 = threadIdx.x; d4 < NUMF / 4; d4 += 512) {
        int d = d4 << 2;
        int r = d & 63, base = d & ~63;
        int slot = r >> 2;
        int t  = (slot & 1) | ((slot >> 3) << 1);
        int st = (slot >> 1) & 1;
        int c  = (slot >> 2) & 1;
        int K0 = base + c * 32 + 16 * (t >> 1) + 2 * (t & 1) + 8 * st;
        float2 v0 = *(const float2*)(src + K0);
        float2 v1 = *(const float2*)(src + K0 + 4);
        uint2 o;
        o.x = f2h2(v0.x, v0.y);
        o.y = f2h2(v1.x, v1.y);
        *(uint2*)(dst + d) = o;
    }
}

// ---------------- kernel 1: layer-0 GEMM (fp16 mma.sync, fp16 B, 148-CTA split) ----------------
__global__ void __launch_bounds__(288, 1) nn_gemm(
    const __grid_constant__ CUtensorMap tmW,
    const __grid_constant__ CUtensorMap tmB,
    const __grid_constant__ CUtensorMap tmW0h)
{
    extern __shared__ char raw[];
    char* base = (char*)(((uintptr_t)raw + 1023u) & ~(uintptr_t)1023u);
    uint32_t base_u   = smem_u32(base);
    uint32_t mb_full  = base_u;            // STAGES x 8B
    uint32_t mb_empty = base_u + 512;      // STAGES x 8B
    char* tiles       = base + 1024;
    uint32_t tiles_u  = base_u + 1024;

    const int tid  = threadIdx.x;
    const int wid  = tid >> 5;
    const int lane = tid & 31;
    const int bid  = blockIdx.x;

    const int cs = (int)((long long)bid * TOTC / GRID1);        // start chunk
    const int ce = (int)((long long)(bid + 1) * TOTC / GRID1);  // end chunk
    const int nc = ce - cs;                                     // 277 or 278
    const int mt0 = cs / CHPM;
    const int mt1 = (ce - 1) / CHPM;                            // mt0 or mt0+1

    if (tid == 0) {
        for (int s = 0; s < STAGES; s++) {
            mbar_init(mb_full  + s * 8, 1);
            mbar_init(mb_empty + s * 8, 256);
        }
        asm volatile("fence.proxy.async.shared::cta;" ::: "memory");
    }
    __syncthreads();

    if (wid == 8) {
        if (lane == 0) {
            // ---------------- producer ----------------
#define ISSUE(c_, s_) do {                                           \
            int mt_ = (c_) / CHPM;                                   \
            int kc_ = (c_) - mt_ * CHPM;                             \
            const CUtensorMap* mp_ = (mt_ < 32) ? &tmW : &tmB;       \
            uint32_t mb_ = mb_full + (s_) * 8;                       \
            mbar_expect_tx(mb_, STGB);                               \
            uint32_t t_ = tiles_u + (s_) * STGB;                     \
            tma2d(t_,         mp_,   kc_ * 64,      (mt_ & 31) * 128, mb_); \
            tma2d(t_ + 16384, mp_,   kc_ * 64 + 32, (mt_ & 31) * 128, mb_); \
            tma2d(t_ + ASTG, &tmW0h, kc_ * 64,      0,                mb_); \
        } while (0)
            ISSUE(cs, 0); ISSUE(cs + 1, 1); ISSUE(cs + 2, 2);
            int s = 0, ep = 0;
            for (int j = STAGES; j < nc; j++) {
                mbar_wait(mb_empty + s * 8, ep);
                ISSUE(cs + j, s);
                if (++s == STAGES) { s = 0; ep ^= 1; }
            }
#undef ISSUE
        }
    } else {
        // ---------------- consumers ----------------
        const int wm = (wid >> 2) * 64;      // warp M offset (0/64)
        const int wn = (wid & 3) * 64;       // warp N offset (0/64/128/192)
        const int g  = lane >> 2;            // 0..7
        const int t  = lane & 3;             // 0..3

        // A: conflict-free swizzled byte offsets (validated R7); st = kstep&1
        int aoff[2][2];
        #pragma unroll
        for (int s_ = 0; s_ < 2; s_++)
            #pragma unroll
            for (int h_ = 0; h_ < 2; h_++)
                aoff[s_][h_] = ((32 * s_ + 16 * h_ + 8 * (t & 1) + 64 * (t >> 1)) ^ (g << 4));
        // B: one LDS.64 per (ni, kstep); slot = P(t) + 2*st + 4*c
        const int Pt = (t & 1) + 8 * (t >> 1);
        int boff[4];
        #pragma unroll
        for (int ks = 0; ks < 4; ks++)
            boff[ks] = (((Pt + 2 * (ks & 1) + 4 * (ks >> 1)) * 8) ^ (g << 4));

        float c[4][8][4];
        #pragma unroll
        for (int mi = 0; mi < 4; mi++)
            #pragma unroll
            for (int ni = 0; ni < 8; ni++)
                #pragma unroll
                for (int r = 0; r < 4; r++) c[mi][ni][r] = 0.f;

        // local index of the last chunk of part 0 (or -1 if single part)
        const int jb = (mt1 > mt0) ? ((mt0 + 1) * CHPM - 1 - cs) : -1;

        int s = 0, fp = 0;
        for (int j = 0; j < nc; j++) {
            mbar_wait(mb_full + s * 8, fp);
            const char* Ast = tiles + s * STGB;
            const char* Bst = Ast + ASTG;

            #pragma unroll
            for (int ks = 0; ks < 4; ks++) {
                const char* Asub = Ast + (ks >> 1) * 16384;
                const int st = ks & 1;
                uint32_t a[4][4];
                #pragma unroll
                for (int mi = 0; mi < 4; mi++) {
                    const char* pr = Asub + (wm + mi * 16 + g) * 128;
                    float2 v00 = *(const float2*)(pr + aoff[st][0]);
                    float2 v10 = *(const float2*)(pr + 1024 + aoff[st][0]);
                    float2 v01 = *(const float2*)(pr + aoff[st][1]);
                    float2 v11 = *(const float2*)(pr + 1024 + aoff[st][1]);
                    a[mi][0] = f2h2(v00.x, v00.y);
                    a[mi][1] = f2h2(v10.x, v10.y);
                    a[mi][2] = f2h2(v01.x, v01.y);
                    a[mi][3] = f2h2(v11.x, v11.y);
                }
                uint32_t b[8][2];
                #pragma unroll
                for (int ni = 0; ni < 8; ni++) {
                    uint2 v = *(const uint2*)(Bst + (wn + ni * 8 + g) * 128 + boff[ks]);
                    b[ni][0] = v.x; b[ni][1] = v.y;
                }
                #pragma unroll
                for (int mi = 0; mi < 4; mi++)
                    #pragma unroll
                    for (int ni = 0; ni < 8; ni++)
                        mma_f16(c[mi][ni], a[mi], b[ni]);
            }
            mbar_arrive(mb_empty + s * 8);
            if (++s == STAGES) { s = 0; fp ^= 1; }

            if (j == jb) {
                // flush part 0, reset accumulators
                float* dst = g_part[bid][0];
                #pragma unroll
                for (int ni = 0; ni < 8; ni++) {
                    const int col = wn + ni * 8 + (t << 1);
                    #pragma unroll
                    for (int mi = 0; mi < 4; mi++) {
                        const int r = wm + mi * 16 + g;
                        *(float2*)(dst + (size_t)r * 256 + col)       = make_float2(c[mi][ni][0], c[mi][ni][1]);
                        *(float2*)(dst + (size_t)(r + 8) * 256 + col) = make_float2(c[mi][ni][2], c[mi][ni][3]);
                        c[mi][ni][0] = c[mi][ni][1] = c[mi][ni][2] = c[mi][ni][3] = 0.f;
                    }
                }
            }
        }

        // final flush (part 1 if two parts, else part 0)
        {
            float* dst = g_part[bid][(mt1 > mt0) ? 1 : 0];
            #pragma unroll
            for (int ni = 0; ni < 8; ni++) {
                const int col = wn + ni * 8 + (t << 1);
                #pragma unroll
                for (int mi = 0; mi < 4; mi++) {
                    const int r = wm + mi * 16 + g;
                    *(float2*)(dst + (size_t)r * 256 + col)       = make_float2(c[mi][ni][0], c[mi][ni][1]);
                    *(float2*)(dst + (size_t)(r + 8) * 256 + col) = make_float2(c[mi][ni][2], c[mi][ni][3]);
                }
            }
        }
    }
}

// ---------------- kernel 1.5: reduce partials -> dense g_acc (+b0) ----------------
__device__ __forceinline__ int cover_cta(int c) {
    return (int)(((long long)(c + 1) * GRID1 - 1) / TOTC);
}
__device__ __forceinline__ int gather_parts(int mt, const float** ptr) {
    int c0 = mt * CHPM;
    int iA = cover_cta(c0);
    int iB = cover_cta(c0 + CHPM - 1);
    int n = 0;
    for (int i = iA; i <= iB && n < 4; i++) {
        int si = (int)((long long)i * TOTC / GRID1);
        int slot = (si / CHPM == mt) ? 0 : 1;
        ptr[n++] = g_part[i][slot];
    }
    return n;
}

__global__ void __launch_bounds__(256) nn_reduce(const float* __restrict__ b0) {
    const int mt   = blockIdx.x >> 3;       // M-tile 0..63
    const int slab = blockIdx.x & 7;        // rows [slab*16, slab*16+16)
    const float* ps[4];
    const int n = gather_parts(mt, ps);

    const int base = slab * 16 * 256;       // float offset within tile
    float* dst = g_acc + (size_t)mt * 128 * 256 + base;
    const float4* b0v = (const float4*)b0;

    // 16 rows x 256 cols = 1024 float4; 256 threads x 4 iters
    for (int i = threadIdx.x; i < 1024; i += 256) {
        float4 s = b0v[i & 63];
        #pragma unroll 4
        for (int k = 0; k < 4; k++) {
            if (k < n) {
                float4 v = ((const float4*)(ps[k] + base))[i];
                s.x += v.x; s.y += v.y; s.z += v.z; s.w += v.w;
            }
        }
        ((float4*)dst)[i] = s;
    }
}

// ---------------- kernel 2: blend + clip + small MLP head (512 thr, 1 row/warp) ----------------
#define SW1_PITCH 513
#define SW2_PITCH 33
#define SMEM2 ((32*SW1_PITCH + 32*SW2_PITCH + 16*512 + 16*32) * 4)

__global__ void __launch_bounds__(512) nn_head(
    const float* __restrict__ stm,
    const float* __restrict__ W1, const float* __restrict__ b1,
    const float* __restrict__ W2, const float* __restrict__ b2,
    const float* __restrict__ W3, const float* __restrict__ b3,
    float* __restrict__ out)
{
    extern __shared__ float sm[];
    float* sW1 = sm;                               // 32 x 513
    float* sW2 = sW1 + 32 * SW1_PITCH;             // 32 x 33
    float* sl1 = sW2 + 32 * SW2_PITCH;             // 16 warps x 512
    float* sl2 = sl1 + 16 * 512;                   // 16 warps x 32

    int tid = threadIdx.x;
    for (int i = tid; i < 32 * 512; i += 512) sW1[(i >> 9) * SW1_PITCH + (i & 511)] = W1[i];
    for (int i = tid; i < 32 * 32;  i += 512) sW2[(i >> 5) * SW2_PITCH + (i & 31)]  = W2[i];
    __syncthreads();

    int w = tid >> 5, j = tid & 31;
    float* l1 = sl1 + w * 512;
    float* l2 = sl2 + w * 32;
    float bj1 = b1[j], bj2 = b2[j], w3j = W3[j], b3v = b3[0];

    int b = blockIdx.x * 16 + w;
    const float* aw = g_acc + (size_t)b * 256;
    const float* ab = g_acc + (size_t)(4096 + b) * 256;
    float s = stm[b];
    for (int tt = j; tt < 256; tt += 32) {
        float wv = aw[tt], bv = ab[tt];
        float x0 = s * wv + (1.f - s) * bv;
        float x1 = s * bv + (1.f - s) * wv;
        l1[tt]       = fminf(fmaxf(x0, 0.f), 1.f);
        l1[256 + tt] = fminf(fmaxf(x1, 0.f), 1.f);
    }
    __syncwarp();
    float a2 = bj1;
    const float* wr = sW1 + j * SW1_PITCH;
    #pragma unroll 8
    for (int k = 0; k < 512; k++) a2 += wr[k] * l1[k];
    a2 = fminf(fmaxf(a2, 0.f), 1.f);
    l2[j] = a2;
    __syncwarp();
    float a3 = bj2;
    const float* wr2 = sW2 + j * SW2_PITCH;
    #pragma unroll
    for (int k = 0; k < 32; k++) a3 += wr2[k] * l2[k];
    a3 = fminf(fmaxf(a3, 0.f), 1.f);
    float v = w3j * a3;
    #pragma unroll
    for (int o = 16; o > 0; o >>= 1) v += __shfl_xor_sync(0xffffffffu, v, o);
    if (j == 0) out[b] = v + b3v;
}

// ---------------- host ----------------
typedef CUresult (*EncodeFn)(CUtensorMap*, CUtensorMapDataType, cuuint32_t, void*,
                             const cuuint64_t*, const cuuint64_t*, const cuuint32_t*, const cuuint32_t*,
                             CUtensorMapInterleave, CUtensorMapSwizzle,
                             CUtensorMapL2promotion, CUtensorMapFloatOOBfill);

static EncodeFn get_encoder() {
    void* p = nullptr;
    cudaDriverEntryPointQueryResult qr;
    cudaGetDriverEntryPointByVersion("cuTensorMapEncodeTiled", &p, 12000, cudaEnableDefault, &qr);
    return (EncodeFn)p;
}

static void encode_f32(CUtensorMap* m, const void* ptr, unsigned long long rows) {
    cuuint64_t dims[2]    = { (cuuint64_t)NUMF, (cuuint64_t)rows };
    cuuint64_t strides[1] = { (cuuint64_t)NUMF * 4ull };
    cuuint32_t box[2]     = { 32u, 128u };      // 128B x 128 rows, SW128
    cuuint32_t es[2]      = { 1u, 1u };
    get_encoder()(m, CU_TENSOR_MAP_DATA_TYPE_FLOAT32, 2, (void*)ptr, dims, strides, box, es,
       CU_TENSOR_MAP_INTERLEAVE_NONE, CU_TENSOR_MAP_SWIZZLE_128B,
       CU_TENSOR_MAP_L2_PROMOTION_L2_128B, CU_TENSOR_MAP_FLOAT_OOB_FILL_NONE);
}

static void encode_f16(CUtensorMap* m, const void* ptr, unsigned long long rows) {
    cuuint64_t dims[2]    = { (cuuint64_t)NUMF, (cuuint64_t)rows };
    cuuint64_t strides[1] = { (cuuint64_t)NUMF * 2ull };
    cuuint32_t box[2]     = { 64u, 256u };      // 128B x 256 rows, SW128
    cuuint32_t es[2]      = { 1u, 1u };
    get_encoder()(m, CU_TENSOR_MAP_DATA_TYPE_FLOAT16, 2, (void*)ptr, dims, strides, box, es,
       CU_TENSOR_MAP_INTERLEAVE_NONE, CU_TENSOR_MAP_SWIZZLE_128B,
       CU_TENSOR_MAP_L2_PROMOTION_L2_128B, CU_TENSOR_MAP_FLOAT_OOB_FILL_NONE);
}

extern "C" void kernel_launch(void* const* d_in, const int* in_sizes, int n_in,
                              void* d_out, int out_size) {
    const float* wf  = (const float*)d_in[0];
    const float* bf  = (const float*)d_in[1];
    const float* stm = (const float*)d_in[2];
    const float* W0  = (const float*)d_in[3];
    const float* b0  = (const float*)d_in[4];
    const float* W1  = (const float*)d_in[5];
    const float* b1  = (const float*)d_in[6];
    const float* W2  = (const float*)d_in[7];
    const float* b2  = (const float*)d_in[8];
    const float* W3  = (const float*)d_in[9];
    const float* b3  = (const float*)d_in[10];
    float* out = (float*)d_out;

    void* w0h_ptr = nullptr;
    cudaGetSymbolAddress(&w0h_ptr, g_w0h);

    CUtensorMap mW, mB, mW0h;
    encode_f32(&mW,  wf, 4096);
    encode_f32(&mB,  bf, 4096);
    encode_f16(&mW0h, w0h_ptr, 256);

    cudaFuncSetAttribute(nn_gemm, cudaFuncAttributeMaxDynamicSharedMemorySize, SMEM1);
    cudaFuncSetAttribute(nn_head, cudaFuncAttributeMaxDynamicSharedMemorySize, SMEM2);

    nn_cvt<<<256, 512>>>(W0);
    nn_gemm<<<GRID1, 288, SMEM1>>>(mW, mB, mW0h);
    nn_reduce<<<512, 256>>>(b0);
    nn_head<<<256, 512, SMEM2>>>(stm, W1, b1, W2, b2, W3, b3, out);
}

// round 14
// speedup vs baseline: 6.2703x; 1.0402x over previous
#include <cuda_runtime.h>
#include <cuda.h>
#include <cuda_fp16.h>
#include <cstdint>

// ---------------- constants ----------------
#define NUMF    41024
#define KCHUNK  64                  // k-values per pipeline chunk (= 4 k16 mma steps)
#define CHPM    641                 // chunks per M-tile (41024/64)
#define NMT     64                  // M-tiles (32 white + 32 black)
#define TOTC    (NMT * CHPM)        // 41024 total chunk-columns
#define GRID1   148                 // one CTA per SM
#define STAGES  3
#define ASTG    32768               // A: 2 sub-tiles x (128 rows x 128B) fp32
#define BSTG    32768               // B: 256 rows x 128B fp16 (64 k)
#define STGB    (ASTG + BSTG)       // 65536
#define SMEM1   (2048 + STAGES * STGB)   // 198656

// per-CTA partials: [cta][part 0/1][128 rows x 256 neurons]
__device__ float g_part[GRID1][2][128 * 256];
// dense accumulator (+b0): rows 0..4095 white, 4096..8191 black
__device__ float g_acc[8192 * 256];
// W0 pre-converted to fp16, fragment-packed per 64-half group
__device__ __align__(1024) __half g_w0h[256 * NUMF];

// ---------------- device helpers ----------------
__device__ __forceinline__ uint32_t smem_u32(const void* p) {
    uint32_t a;
    asm("{ .reg .u64 t; cvta.to.shared.u64 t, %1; cvt.u32.u64 %0, t; }" : "=r"(a) : "l"(p));
    return a;
}
__device__ __forceinline__ void mbar_init(uint32_t a, uint32_t c) {
    asm volatile("mbarrier.init.shared.b64 [%0], %1;" :: "r"(a), "r"(c) : "memory");
}
__device__ __forceinline__ void mbar_expect_tx(uint32_t a, uint32_t b) {
    asm volatile("mbarrier.arrive.expect_tx.shared.b64 _, [%0], %1;" :: "r"(a), "r"(b) : "memory");
}
__device__ __forceinline__ void mbar_arrive(uint32_t a) {
    asm volatile("mbarrier.arrive.shared.b64 _, [%0];" :: "r"(a) : "memory");
}
__device__ __forceinline__ void mbar_wait(uint32_t mbar, uint32_t parity) {
    asm volatile(
        "{\n\t.reg .pred P;\n\t"
        "LW_%=:\n\t"
        "mbarrier.try_wait.parity.acquire.cta.shared::cta.b64 P, [%0], %1, 0x989680;\n\t"
        "@P bra.uni LD_%=;\n\t"
        "bra.uni LW_%=;\n\t"
        "LD_%=:\n\t}"
        :: "r"(mbar), "r"(parity) : "memory");
}
__device__ __forceinline__ void tma2d(uint32_t dst, const CUtensorMap* m, int x, int y, uint32_t mbar) {
    asm volatile(
        "cp.async.bulk.tensor.2d.shared::cta.global.tile.mbarrier::complete_tx::bytes "
        "[%0], [%1, {%2, %3}], [%4];"
        :: "r"(dst), "l"(m), "r"(x), "r"(y), "r"(mbar) : "memory");
}
// pack two fp32 -> f16x2 {lo, hi}
__device__ __forceinline__ uint32_t f2h2(float lo, float hi) {
    uint32_t r;
    asm("cvt.rn.f16x2.f32 %0, %2, %1;" : "=r"(r) : "f"(lo), "f"(hi));
    return r;
}
__device__ __forceinline__ void mma_f16(float* c, const uint32_t* a, const uint32_t* b) {
    asm volatile(
        "mma.sync.aligned.m16n8k16.row.col.f32.f16.f16.f32 "
        "{%0,%1,%2,%3}, {%4,%5,%6,%7}, {%8,%9}, {%0,%1,%2,%3};"
        : "+f"(c[0]), "+f"(c[1]), "+f"(c[2]), "+f"(c[3])
        : "r"(a[0]), "r"(a[1]), "r"(a[2]), "r"(a[3]), "r"(b[0]), "r"(b[1]));
}

// ---------------- kernel 0: convert W0 -> fragment-packed fp16 (vectorized) ----------------
__global__ void __launch_bounds__(512) nn_cvt(const float* __restrict__ W0) {
    const int n = blockIdx.x;                 // 0..255
    const float* src = W0 + (size_t)n * NUMF;
    __half* dst = g_w0h + (size_t)n * NUMF;
    for (int d4 = threadIdx.x; d4 < NUMF / 4; d4 += 512) {
        int d = d4 << 2;
        int r = d & 63, base = d & ~63;
        int slot = r >> 2;
        int t  = (slot & 1) | ((slot >> 3) << 1);
        int st = (slot >> 1) & 1;
        int c  = (slot >> 2) & 1;
        int K0 = base + c * 32 + 16 * (t >> 1) + 2 * (t & 1) + 8 * st;
        float2 v0 = *(const float2*)(src + K0);
        float2 v1 = *(const float2*)(src + K0 + 4);
        uint2 o;
        o.x = f2h2(v0.x, v0.y);
        o.y = f2h2(v1.x, v1.y);
        *(uint2*)(dst + d) = o;
    }
}

// ---------------- kernel 1: layer-0 GEMM (fp16 mma.sync, fp16 B, 148-CTA split) ----------------
__global__ void __launch_bounds__(288, 1) nn_gemm(
    const __grid_constant__ CUtensorMap tmW,
    const __grid_constant__ CUtensorMap tmB,
    const __grid_constant__ CUtensorMap tmW0h)
{
    extern __shared__ char raw[];
    char* base = (char*)(((uintptr_t)raw + 1023u) & ~(uintptr_t)1023u);
    uint32_t base_u   = smem_u32(base);
    uint32_t mb_full  = base_u;            // STAGES x 8B
    uint32_t mb_empty = base_u + 512;      // STAGES x 8B
    char* tiles       = base + 1024;
    uint32_t tiles_u  = base_u + 1024;

    const int tid  = threadIdx.x;
    const int wid  = tid >> 5;
    const int lane = tid & 31;
    const int bid  = blockIdx.x;

    const int cs = (int)((long long)bid * TOTC / GRID1);        // start chunk
    const int ce = (int)((long long)(bid + 1) * TOTC / GRID1);  // end chunk
    const int nc = ce - cs;                                     // 277 or 278
    const int mt0 = cs / CHPM;
    const int mt1 = (ce - 1) / CHPM;                            // mt0 or mt0+1

    if (tid == 0) {
        for (int s = 0; s < STAGES; s++) {
            mbar_init(mb_full  + s * 8, 1);
            mbar_init(mb_empty + s * 8, 256);
        }
        asm volatile("fence.proxy.async.shared::cta;" ::: "memory");
    }
    __syncthreads();

    if (wid == 8) {
        if (lane == 0) {
            // ---------------- producer ----------------
#define ISSUE(c_, s_) do {                                           \
            int mt_ = (c_) / CHPM;                                   \
            int kc_ = (c_) - mt_ * CHPM;                             \
            const CUtensorMap* mp_ = (mt_ < 32) ? &tmW : &tmB;       \
            uint32_t mb_ = mb_full + (s_) * 8;                       \
            mbar_expect_tx(mb_, STGB);                               \
            uint32_t t_ = tiles_u + (s_) * STGB;                     \
            tma2d(t_,         mp_,   kc_ * 64,      (mt_ & 31) * 128, mb_); \
            tma2d(t_ + 16384, mp_,   kc_ * 64 + 32, (mt_ & 31) * 128, mb_); \
            tma2d(t_ + ASTG, &tmW0h, kc_ * 64,      0,                mb_); \
        } while (0)
            ISSUE(cs, 0); ISSUE(cs + 1, 1); ISSUE(cs + 2, 2);
            int s = 0, ep = 0;
            for (int j = STAGES; j < nc; j++) {
                mbar_wait(mb_empty + s * 8, ep);
                ISSUE(cs + j, s);
                if (++s == STAGES) { s = 0; ep ^= 1; }
            }
#undef ISSUE
        }
    } else {
        // ---------------- consumers ----------------
        const int wm = (wid >> 2) * 64;      // warp M offset (0/64)
        const int wn = (wid & 3) * 64;       // warp N offset (0/64/128/192)
        const int g  = lane >> 2;            // 0..7
        const int t  = lane & 3;             // 0..3

        // A: conflict-free swizzled byte offsets (validated R7); st = kstep&1
        int aoff[2][2];
        #pragma unroll
        for (int s_ = 0; s_ < 2; s_++)
            #pragma unroll
            for (int h_ = 0; h_ < 2; h_++)
                aoff[s_][h_] = ((32 * s_ + 16 * h_ + 8 * (t & 1) + 64 * (t >> 1)) ^ (g << 4));
        // B: one LDS.64 per (ni, kstep); slot = P(t) + 2*st + 4*c
        const int Pt = (t & 1) + 8 * (t >> 1);
        int boff[4];
        #pragma unroll
        for (int ks = 0; ks < 4; ks++)
            boff[ks] = (((Pt + 2 * (ks & 1) + 4 * (ks >> 1)) * 8) ^ (g << 4));

        float c[4][8][4];
        #pragma unroll
        for (int mi = 0; mi < 4; mi++)
            #pragma unroll
            for (int ni = 0; ni < 8; ni++)
                #pragma unroll
                for (int r = 0; r < 4; r++) c[mi][ni][r] = 0.f;

        // local index of the last chunk of part 0 (or -1 if single part)
        const int jb = (mt1 > mt0) ? ((mt0 + 1) * CHPM - 1 - cs) : -1;

        int s = 0, fp = 0;
        for (int j = 0; j < nc; j++) {
            mbar_wait(mb_full + s * 8, fp);
            const char* Ast = tiles + s * STGB;
            const char* Bst = Ast + ASTG;

            #pragma unroll
            for (int ks = 0; ks < 4; ks++) {
                const char* Asub = Ast + (ks >> 1) * 16384;
                const int st = ks & 1;
                uint32_t a[4][4];
                #pragma unroll
                for (int mi = 0; mi < 4; mi++) {
                    const char* pr = Asub + (wm + mi * 16 + g) * 128;
                    float2 v00 = *(const float2*)(pr + aoff[st][0]);
                    float2 v10 = *(const float2*)(pr + 1024 + aoff[st][0]);
                    float2 v01 = *(const float2*)(pr + aoff[st][1]);
                    float2 v11 = *(const float2*)(pr + 1024 + aoff[st][1]);
                    a[mi][0] = f2h2(v00.x, v00.y);
                    a[mi][1] = f2h2(v10.x, v10.y);
                    a[mi][2] = f2h2(v01.x, v01.y);
                    a[mi][3] = f2h2(v11.x, v11.y);
                }
                uint32_t b[8][2];
                #pragma unroll
                for (int ni = 0; ni < 8; ni++) {
                    uint2 v = *(const uint2*)(Bst + (wn + ni * 8 + g) * 128 + boff[ks]);
                    b[ni][0] = v.x; b[ni][1] = v.y;
                }
                #pragma unroll
                for (int mi = 0; mi < 4; mi++)
                    #pragma unroll
                    for (int ni = 0; ni < 8; ni++)
                        mma_f16(c[mi][ni], a[mi], b[ni]);
            }
            mbar_arrive(mb_empty + s * 8);
            if (++s == STAGES) { s = 0; fp ^= 1; }

            if (j == jb) {
                // flush part 0, reset accumulators
                float* dst = g_part[bid][0];
                #pragma unroll
                for (int ni = 0; ni < 8; ni++) {
                    const int col = wn + ni * 8 + (t << 1);
                    #pragma unroll
                    for (int mi = 0; mi < 4; mi++) {
                        const int r = wm + mi * 16 + g;
                        *(float2*)(dst + (size_t)r * 256 + col)       = make_float2(c[mi][ni][0], c[mi][ni][1]);
                        *(float2*)(dst + (size_t)(r + 8) * 256 + col) = make_float2(c[mi][ni][2], c[mi][ni][3]);
                        c[mi][ni][0] = c[mi][ni][1] = c[mi][ni][2] = c[mi][ni][3] = 0.f;
                    }
                }
            }
        }

        // final flush (part 1 if two parts, else part 0)
        {
            float* dst = g_part[bid][(mt1 > mt0) ? 1 : 0];
            #pragma unroll
            for (int ni = 0; ni < 8; ni++) {
                const int col = wn + ni * 8 + (t << 1);
                #pragma unroll
                for (int mi = 0; mi < 4; mi++) {
                    const int r = wm + mi * 16 + g;
                    *(float2*)(dst + (size_t)r * 256 + col)       = make_float2(c[mi][ni][0], c[mi][ni][1]);
                    *(float2*)(dst + (size_t)(r + 8) * 256 + col) = make_float2(c[mi][ni][2], c[mi][ni][3]);
                }
            }
        }
    }
}

// ---------------- kernel 1.5: reduce partials -> dense g_acc (+b0) ----------------
__device__ __forceinline__ int cover_cta(int c) {
    return (int)(((long long)(c + 1) * GRID1 - 1) / TOTC);
}
__device__ __forceinline__ int gather_parts(int mt, const float** ptr) {
    int c0 = mt * CHPM;
    int iA = cover_cta(c0);
    int iB = cover_cta(c0 + CHPM - 1);
    int n = 0;
    for (int i = iA; i <= iB && n < 4; i++) {
        int si = (int)((long long)i * TOTC / GRID1);
        int slot = (si / CHPM == mt) ? 0 : 1;
        ptr[n++] = g_part[i][slot];
    }
    return n;
}

__global__ void __launch_bounds__(256) nn_reduce(const float* __restrict__ b0) {
    const int mt   = blockIdx.x >> 3;       // M-tile 0..63
    const int slab = blockIdx.x & 7;        // rows [slab*16, slab*16+16)
    const float* ps[4];
    const int n = gather_parts(mt, ps);

    const int base = slab * 16 * 256;       // float offset within tile
    float* dst = g_acc + (size_t)mt * 128 * 256 + base;
    const float4* b0v = (const float4*)b0;

    // 16 rows x 256 cols = 1024 float4; 256 threads x 4 iters
    for (int i = threadIdx.x; i < 1024; i += 256) {
        float4 s = b0v[i & 63];
        #pragma unroll 4
        for (int k = 0; k < 4; k++) {
            if (k < n) {
                float4 v = ((const float4*)(ps[k] + base))[i];
                s.x += v.x; s.y += v.y; s.z += v.z; s.w += v.w;
            }
        }
        ((float4*)dst)[i] = s;
    }
}

// ---------------- kernel 2: blend + clip + small MLP head (vectorized, 4-acc) ----------------
#define SW1_PITCH 516               // floats; 516*4 B row stride, 16B aligned, 8-lane phases conflict-free
#define SW2_PITCH 36
#define SMEM2 ((32*SW1_PITCH + 32*SW2_PITCH + 16*512 + 16*32) * 4)

__device__ __forceinline__ float4 clip4(float4 v) {
    v.x = fminf(fmaxf(v.x, 0.f), 1.f);
    v.y = fminf(fmaxf(v.y, 0.f), 1.f);
    v.z = fminf(fmaxf(v.z, 0.f), 1.f);
    v.w = fminf(fmaxf(v.w, 0.f), 1.f);
    return v;
}

__global__ void __launch_bounds__(512) nn_head(
    const float* __restrict__ stm,
    const float* __restrict__ W1, const float* __restrict__ b1,
    const float* __restrict__ W2, const float* __restrict__ b2,
    const float* __restrict__ W3, const float* __restrict__ b3,
    float* __restrict__ out)
{
    extern __shared__ float sm[];
    float* sW1 = sm;                               // 32 x 516
    float* sW2 = sW1 + 32 * SW1_PITCH;             // 32 x 36
    float* sl1 = sW2 + 32 * SW2_PITCH;             // 16 warps x 512
    float* sl2 = sl1 + 16 * 512;                   // 16 warps x 32

    int tid = threadIdx.x;
    int w = tid >> 5, j = tid & 31;
    int b = blockIdx.x * 16 + w;

    // issue global loads early (latency overlap with smem fill)
    const float4* aw = (const float4*)(g_acc + (size_t)b * 256);
    const float4* ab = (const float4*)(g_acc + (size_t)(4096 + b) * 256);
    float4 wv0 = aw[j],      bv0 = ab[j];
    float4 wv1 = aw[32 + j], bv1 = ab[32 + j];
    float s = stm[b];

    for (int i = tid; i < 32 * 512; i += 512) sW1[(i >> 9) * SW1_PITCH + (i & 511)] = W1[i];
    for (int i = tid; i < 32 * 32;  i += 512) sW2[(i >> 5) * SW2_PITCH + (i & 31)]  = W2[i];
    __syncthreads();

    float4* l14 = (float4*)(sl1 + w * 512);
    float*  l2  = sl2 + w * 32;
    float bj1 = b1[j], bj2 = b2[j], w3j = W3[j], b3v = b3[0];
    const float t1 = 1.f - s;

    {
        float4 x0, x1, y0, y1;
        x0.x = s*wv0.x + t1*bv0.x; x0.y = s*wv0.y + t1*bv0.y; x0.z = s*wv0.z + t1*bv0.z; x0.w = s*wv0.w + t1*bv0.w;
        y0.x = s*bv0.x + t1*wv0.x; y0.y = s*bv0.y + t1*wv0.y; y0.z = s*bv0.z + t1*wv0.z; y0.w = s*bv0.w + t1*wv0.w;
        x1.x = s*wv1.x + t1*bv1.x; x1.y = s*wv1.y + t1*bv1.y; x1.z = s*wv1.z + t1*bv1.z; x1.w = s*wv1.w + t1*bv1.w;
        y1.x = s*bv1.x + t1*wv1.x; y1.y = s*bv1.y + t1*wv1.y; y1.z = s*bv1.z + t1*wv1.z; y1.w = s*bv1.w + t1*wv1.w;
        l14[j]       = clip4(x0);
        l14[32 + j]  = clip4(x1);
        l14[64 + j]  = clip4(y0);
        l14[96 + j]  = clip4(y1);
    }
    __syncwarp();

    // L1: 512-dot with 4 independent accumulator chains, float4 LDS
    float a0 = bj1, a1 = 0.f, a2c = 0.f, a3c = 0.f;
    const float4* wr = (const float4*)(sW1 + j * SW1_PITCH);
    #pragma unroll 16
    for (int k = 0; k < 128; k++) {
        float4 v = wr[k], u = l14[k];
        a0  += v.x * u.x;
        a1  += v.y * u.y;
        a2c += v.z * u.z;
        a3c += v.w * u.w;
    }
    float a2 = fminf(fmaxf((a0 + a1) + (a2c + a3c), 0.f), 1.f);
    l2[j] = a2;
    __syncwarp();

    // L2: 32-dot, float4
    float c0 = bj2, c1 = 0.f, c2 = 0.f, c3 = 0.f;
    const float4* wr2 = (const float4*)(sW2 + j * SW2_PITCH);
    const float4* l24 = (const float4*)l2;
    #pragma unroll
    for (int k = 0; k < 8; k++) {
        float4 v = wr2[k], u = l24[k];
        c0 += v.x * u.x; c1 += v.y * u.y; c2 += v.z * u.z; c3 += v.w * u.w;
    }
    float a3 = fminf(fmaxf((c0 + c1) + (c2 + c3), 0.f), 1.f);
    float v = w3j * a3;
    #pragma unroll
    for (int o = 16; o > 0; o >>= 1) v += __shfl_xor_sync(0xffffffffu, v, o);
    if (j == 0) out[b] = v + b3v;
}

// ---------------- host ----------------
typedef CUresult (*EncodeFn)(CUtensorMap*, CUtensorMapDataType, cuuint32_t, void*,
                             const cuuint64_t*, const cuuint64_t*, const cuuint32_t*, const cuuint32_t*,
                             CUtensorMapInterleave, CUtensorMapSwizzle,
                             CUtensorMapL2promotion, CUtensorMapFloatOOBfill);

static EncodeFn get_encoder() {
    void* p = nullptr;
    cudaDriverEntryPointQueryResult qr;
    cudaGetDriverEntryPointByVersion("cuTensorMapEncodeTiled", &p, 12000, cudaEnableDefault, &qr);
    return (EncodeFn)p;
}

static void encode_f32(CUtensorMap* m, const void* ptr, unsigned long long rows) {
    cuuint64_t dims[2]    = { (cuuint64_t)NUMF, (cuuint64_t)rows };
    cuuint64_t strides[1] = { (cuuint64_t)NUMF * 4ull };
    cuuint32_t box[2]     = { 32u, 128u };      // 128B x 128 rows, SW128
    cuuint32_t es[2]      = { 1u, 1u };
    get_encoder()(m, CU_TENSOR_MAP_DATA_TYPE_FLOAT32, 2, (void*)ptr, dims, strides, box, es,
       CU_TENSOR_MAP_INTERLEAVE_NONE, CU_TENSOR_MAP_SWIZZLE_128B,
       CU_TENSOR_MAP_L2_PROMOTION_L2_128B, CU_TENSOR_MAP_FLOAT_OOB_FILL_NONE);
}

static void encode_f16(CUtensorMap* m, const void* ptr, unsigned long long rows) {
    cuuint64_t dims[2]    = { (cuuint64_t)NUMF, (cuuint64_t)rows };
    cuuint64_t strides[1] = { (cuuint64_t)NUMF * 2ull };
    cuuint32_t box[2]     = { 64u, 256u };      // 128B x 256 rows, SW128
    cuuint32_t es[2]      = { 1u, 1u };
    get_encoder()(m, CU_TENSOR_MAP_DATA_TYPE_FLOAT16, 2, (void*)ptr, dims, strides, box, es,
       CU_TENSOR_MAP_INTERLEAVE_NONE, CU_TENSOR_MAP_SWIZZLE_128B,
       CU_TENSOR_MAP_L2_PROMOTION_L2_128B, CU_TENSOR_MAP_FLOAT_OOB_FILL_NONE);
}

extern "C" void kernel_launch(void* const* d_in, const int* in_sizes, int n_in,
                              void* d_out, int out_size) {
    const float* wf  = (const float*)d_in[0];
    const float* bf  = (const float*)d_in[1];
    const float* stm = (const float*)d_in[2];
    const float* W0  = (const float*)d_in[3];
    const float* b0  = (const float*)d_in[4];
    const float* W1  = (const float*)d_in[5];
    const float* b1  = (const float*)d_in[6];
    const float* W2  = (const float*)d_in[7];
    const float* b2  = (const float*)d_in[8];
    const float* W3  = (const float*)d_in[9];
    const float* b3  = (const float*)d_in[10];
    float* out = (float*)d_out;

    void* w0h_ptr = nullptr;
    cudaGetSymbolAddress(&w0h_ptr, g_w0h);

    CUtensorMap mW, mB, mW0h;
    encode_f32(&mW,  wf, 4096);
    encode_f32(&mB,  bf, 4096);
    encode_f16(&mW0h, w0h_ptr, 256);

    cudaFuncSetAttribute(nn_gemm, cudaFuncAttributeMaxDynamicSharedMemorySize, SMEM1);
    cudaFuncSetAttribute(nn_head, cudaFuncAttributeMaxDynamicSharedMemorySize, SMEM2);

    nn_cvt<<<256, 512>>>(W0);
    nn_gemm<<<GRID1, 288, SMEM1>>>(mW, mB, mW0h);
    nn_reduce<<<512, 256>>>(b0);
    nn_head<<<256, 512, SMEM2>>>(stm, W1, b1, W2, b2, W3, b3, out);
}